// round 1
// baseline (speedup 1.0000x reference)
#include <cuda_runtime.h>
#include <math.h>

// Problem constants
#define BB 65536
#define FDIM 267
#define HDIM 256
#define LDIM 64
#define KCODE 1024

// ---------------- scratch (device globals; no runtime allocation) ----------------
__device__ float g_h1[BB * HDIM];
__device__ float g_h2[BB * HDIM];
__device__ float g_mu[BB * LDIM];
__device__ float g_q[BB * LDIM];
__device__ int   g_idx[BB];
__device__ float g_esq[KCODE];
__device__ int   g_counts[KCODE];
__device__ float g_partials[BB / 8];   // 8192 per-block loss partials

// ---------------- generic fp32 GEMM: C[M,N] = act( [A0|A1][M,K] * W[N,K]^T + b ) ----------------
// 128x128 block tile, 8x8 per-thread tile, BK=8, 256 threads.
__global__ void __launch_bounds__(256, 2) gemm_bias_kernel(
    const float* __restrict__ A0, int W0,
    const float* __restrict__ A1, int W1,
    const float* __restrict__ W, const float* __restrict__ bias,
    float* __restrict__ C, int N, int K, int relu)
{
    __shared__ float As[8][128];
    __shared__ float Bs[8][128];

    const int bm  = blockIdx.y * 128;
    const int bn  = blockIdx.x * 128;
    const int tid = threadIdx.x;
    const int tx  = tid & 15;   // 0..15 -> n
    const int ty  = tid >> 4;   // 0..15 -> m
    const int lm  = tid >> 1;   // 0..127 loader row
    const int lk0 = (tid & 1) * 4;

    float acc[8][8];
    #pragma unroll
    for (int i = 0; i < 8; i++)
        #pragma unroll
        for (int j = 0; j < 8; j++) acc[i][j] = 0.f;

    for (int k0 = 0; k0 < K; k0 += 8) {
        // load A tile (handles concat of A0|A1)
        {
            const int m = bm + lm;
            #pragma unroll
            for (int j = 0; j < 4; j++) {
                int kk = k0 + lk0 + j;
                float v = 0.f;
                if (kk < K)
                    v = (kk < W0) ? A0[(size_t)m * W0 + kk]
                                  : A1[(size_t)m * W1 + (kk - W0)];
                As[lk0 + j][lm] = v;
            }
        }
        // load W tile: Bs[k][n] = W[(bn+n)*K + kk]
        {
            const int n = bn + lm;
            #pragma unroll
            for (int j = 0; j < 4; j++) {
                int kk = k0 + lk0 + j;
                float v = 0.f;
                if (kk < K && n < N) v = W[(size_t)n * K + kk];
                Bs[lk0 + j][lm] = v;
            }
        }
        __syncthreads();

        #pragma unroll
        for (int k = 0; k < 8; k++) {
            float4 a0 = *(const float4*)&As[k][ty * 8];
            float4 a1 = *(const float4*)&As[k][ty * 8 + 4];
            float4 b0 = *(const float4*)&Bs[k][tx * 8];
            float4 b1 = *(const float4*)&Bs[k][tx * 8 + 4];
            float a[8] = {a0.x, a0.y, a0.z, a0.w, a1.x, a1.y, a1.z, a1.w};
            float b[8] = {b0.x, b0.y, b0.z, b0.w, b1.x, b1.y, b1.z, b1.w};
            #pragma unroll
            for (int i = 0; i < 8; i++)
                #pragma unroll
                for (int j = 0; j < 8; j++)
                    acc[i][j] += a[i] * b[j];
        }
        __syncthreads();
    }

    // epilogue
    #pragma unroll
    for (int i = 0; i < 8; i++) {
        const int m = bm + ty * 8 + i;
        #pragma unroll
        for (int j = 0; j < 8; j++) {
            const int n = bn + tx * 8 + j;
            if (n < N) {
                float v = acc[i][j] + bias[n];
                if (relu) v = fmaxf(v, 0.f);
                C[(size_t)m * N + n] = v;
            }
        }
    }
}

// ---------------- ||e_k||^2 for each codebook column ----------------
__global__ void esq_kernel(const float* __restrict__ embed)
{
    int k = blockIdx.x * blockDim.x + threadIdx.x;
    if (k < KCODE) {
        float s = 0.f;
        #pragma unroll 8
        for (int l = 0; l < LDIM; l++) {
            float e = embed[l * KCODE + k];
            s += e * e;
        }
        g_esq[k] = s;
    }
}

__global__ void zero_counts_kernel()
{
    int i = blockIdx.x * blockDim.x + threadIdx.x;
    if (i < KCODE) g_counts[i] = 0;
}

// ---------------- VQ argmin: 128 rows/block, smem-tiled over codebook ----------------
// score_k = ||e_k||^2 - 2 mu.e_k  (||mu||^2 dropped: doesn't change argmin)
__global__ void __launch_bounds__(256) vq_argmin_kernel(const float* __restrict__ embed)
{
    __shared__ float mu_s[128][65];
    __shared__ float e_s[64][64];
    __shared__ float esq_s[64];

    const int r0  = blockIdx.x * 128;
    const int tid = threadIdx.x;
    const int tc  = tid & 7;    // code sub-group (8 codes)
    const int tr  = tid >> 3;   // row group (4 rows), 0..31

    // load mu tile
    for (int i = tid; i < 128 * 64; i += 256) {
        int r = i >> 6, l = i & 63;
        mu_s[r][l] = g_mu[(size_t)(r0 + r) * LDIM + l];
    }
    __syncthreads();

    float best[4];
    int   bidx[4];
    #pragma unroll
    for (int i = 0; i < 4; i++) { best[i] = 3.4e38f; bidx[i] = 0; }

    for (int c0 = 0; c0 < KCODE; c0 += 64) {
        __syncthreads();
        for (int i = tid; i < 64 * 64; i += 256) {
            int l = i >> 6, c = i & 63;
            e_s[l][c] = embed[l * KCODE + c0 + c];
        }
        if (tid < 64) esq_s[tid] = g_esq[c0 + tid];
        __syncthreads();

        float dot[4][8];
        #pragma unroll
        for (int i = 0; i < 4; i++)
            #pragma unroll
            for (int j = 0; j < 8; j++) dot[i][j] = 0.f;

        #pragma unroll 4
        for (int l = 0; l < 64; l++) {
            float ev[8], mv[4];
            #pragma unroll
            for (int j = 0; j < 8; j++) ev[j] = e_s[l][tc * 8 + j];
            #pragma unroll
            for (int i = 0; i < 4; i++) mv[i] = mu_s[tr * 4 + i][l];
            #pragma unroll
            for (int i = 0; i < 4; i++)
                #pragma unroll
                for (int j = 0; j < 8; j++)
                    dot[i][j] += mv[i] * ev[j];
        }

        #pragma unroll
        for (int i = 0; i < 4; i++)
            #pragma unroll
            for (int j = 0; j < 8; j++) {
                int code = c0 + tc * 8 + j;
                float sc = esq_s[tc * 8 + j] - 2.f * dot[i][j];
                if (sc < best[i]) { best[i] = sc; bidx[i] = code; }  // ascending scan -> first-min kept
            }
    }

    // reduce across the 8 code-subgroup lanes (consecutive lanes in warp), ties -> lower index
    #pragma unroll
    for (int i = 0; i < 4; i++) {
        #pragma unroll
        for (int s = 4; s >= 1; s >>= 1) {
            float osc = __shfl_down_sync(0xffffffffu, best[i], s, 8);
            int   oid = __shfl_down_sync(0xffffffffu, bidx[i], s, 8);
            if (osc < best[i] || (osc == best[i] && oid < bidx[i])) {
                best[i] = osc; bidx[i] = oid;
            }
        }
        if (tc == 0) g_idx[r0 + tr * 4 + i] = bidx[i];
    }
}

// ---------------- gather codebook rows, loss partials, histogram ----------------
// 8 rows per block (1 warp per row); deterministic loss partial per block.
__global__ void __launch_bounds__(256) gather_loss_kernel(const float* __restrict__ embed)
{
    __shared__ float ps[8];
    const int w    = threadIdx.x >> 5;
    const int lane = threadIdx.x & 31;
    const int row  = blockIdx.x * 8 + w;
    const int idx  = g_idx[row];

    float s = 0.f;
    #pragma unroll
    for (int h = 0; h < 2; h++) {
        int l = lane + 32 * h;
        float e = embed[l * KCODE + idx];
        g_q[(size_t)row * LDIM + l] = e;
        float d = e - g_mu[(size_t)row * LDIM + l];
        s += d * d;
    }
    #pragma unroll
    for (int off = 16; off; off >>= 1) s += __shfl_down_sync(0xffffffffu, s, off);
    if (lane == 0) {
        ps[w] = s;
        atomicAdd(&g_counts[idx], 1);   // integer atomics: order-independent -> deterministic
    }
    __syncthreads();
    if (threadIdx.x == 0) {
        float t = 0.f;
        #pragma unroll
        for (int i = 0; i < 8; i++) t += ps[i];
        g_partials[blockIdx.x] = t;
    }
}

// ---------------- finalize: loss + perplexity scalars ----------------
__global__ void __launch_bounds__(256) finalize_kernel(float* __restrict__ out)
{
    __shared__ float red[256];
    const int t = threadIdx.x;

    float s = 0.f;
    for (int i = t; i < BB / 8; i += 256) s += g_partials[i];
    red[t] = s;
    for (int st = 128; st > 0; st >>= 1) {
        __syncthreads();
        if (t < st) red[t] += red[t + st];
    }
    __syncthreads();
    float loss = red[0] / (float)((size_t)BB * LDIM);
    __syncthreads();

    float e = 0.f;
    for (int k = t; k < KCODE; k += 256) {
        float p = (float)g_counts[k] / (float)BB;
        e += p * logf(p + 1e-10f);
    }
    red[t] = e;
    for (int st = 128; st > 0; st >>= 1) {
        __syncthreads();
        if (t < st) red[t] += red[t + st];
    }
    __syncthreads();
    if (t == 0) {
        out[(size_t)BB * FDIM]     = loss;
        out[(size_t)BB * FDIM + 1] = expf(-red[0]);
    }
}

// ---------------- host launcher ----------------
extern "C" void kernel_launch(void* const* d_in, const int* in_sizes, int n_in,
                              void* d_out, int out_size)
{
    const float* x     = (const float*)d_in[0];
    const float* c     = (const float*)d_in[1];
    const float* fc1_w = (const float*)d_in[2];
    const float* fc1_b = (const float*)d_in[3];
    const float* fc2_w = (const float*)d_in[4];
    const float* fc2_b = (const float*)d_in[5];
    const float* fc3_w = (const float*)d_in[6];
    const float* fc3_b = (const float*)d_in[7];
    const float* mu_w  = (const float*)d_in[8];
    const float* mu_b  = (const float*)d_in[9];
    const float* fc4_w = (const float*)d_in[10];
    const float* fc4_b = (const float*)d_in[11];
    const float* fc5_w = (const float*)d_in[12];
    const float* fc5_b = (const float*)d_in[13];
    const float* fc6_w = (const float*)d_in[14];
    const float* fc6_b = (const float*)d_in[15];
    const float* out_w = (const float*)d_in[16];
    const float* out_b = (const float*)d_in[17];
    const float* embed = (const float*)d_in[18];
    float* out = (float*)d_out;

    float *h1, *h2, *mu, *q;
    cudaGetSymbolAddress((void**)&h1, g_h1);
    cudaGetSymbolAddress((void**)&h2, g_h2);
    cudaGetSymbolAddress((void**)&mu, g_mu);
    cudaGetSymbolAddress((void**)&q,  g_q);

    const dim3 blk(256);
    const dim3 grid256(2, BB / 128);   // N=256
    const dim3 grid64(1, BB / 128);    // N=64
    const dim3 grid267(3, BB / 128);   // N=267

    // --- encoder ---
    gemm_bias_kernel<<<grid256, blk>>>(x, FDIM, c, FDIM, fc1_w, fc1_b, h1, HDIM, 2 * FDIM, 1);
    gemm_bias_kernel<<<grid256, blk>>>(h1, HDIM, nullptr, 0, fc2_w, fc2_b, h2, HDIM, HDIM, 1);
    gemm_bias_kernel<<<grid256, blk>>>(h2, HDIM, nullptr, 0, fc3_w, fc3_b, h1, HDIM, HDIM, 1);
    gemm_bias_kernel<<<grid64,  blk>>>(h1, HDIM, nullptr, 0, mu_w,  mu_b,  mu, LDIM, HDIM, 0);

    // --- vector quantizer ---
    esq_kernel<<<4, 256>>>(embed);
    zero_counts_kernel<<<4, 256>>>();
    vq_argmin_kernel<<<BB / 128, 256>>>(embed);
    gather_loss_kernel<<<BB / 8, 256>>>(embed);

    // --- decoder (q_st == quantize numerically) ---
    gemm_bias_kernel<<<grid256, blk>>>(q, LDIM, c, FDIM, fc4_w, fc4_b, h2, HDIM, LDIM + FDIM, 1);
    gemm_bias_kernel<<<grid256, blk>>>(h2, HDIM, nullptr, 0, fc5_w, fc5_b, h1, HDIM, HDIM, 1);
    gemm_bias_kernel<<<grid256, blk>>>(h1, HDIM, nullptr, 0, fc6_w, fc6_b, h2, HDIM, HDIM, 1);
    gemm_bias_kernel<<<grid267, blk>>>(h2, HDIM, nullptr, 0, out_w, out_b, out, FDIM, HDIM, 0);

    // --- scalars ---
    finalize_kernel<<<1, 256>>>(out);
}

// round 4
// speedup vs baseline: 1.6998x; 1.6998x over previous
#include <cuda_runtime.h>
#include <cstdint>
#include <math.h>

#define BB 65536
#define FDIM 267
#define HDIM 256
#define LDIM 64
#define KCODE 1024

// ---------------- scratch (device globals) ----------------
__device__ float g_h1[BB * HDIM];
__device__ float g_h2[BB * HDIM];
__device__ float g_mu[BB * LDIM];
__device__ float g_q[BB * LDIM];
__device__ int   g_idx[BB];
__device__ float g_esq[KCODE];
__device__ int   g_counts[KCODE];
__device__ float g_partials[BB / 8];
__device__ float g_et[KCODE * LDIM];   // transposed codebook [code][l]

// ---------------- helpers ----------------
__device__ __forceinline__ void split_tf32(float v, uint32_t& hi, uint32_t& lo) {
    uint32_t h;
    asm("cvt.rna.tf32.f32 %0, %1;" : "=r"(h) : "f"(v));
    float lf = v - __uint_as_float(h);
    asm("cvt.rna.tf32.f32 %0, %1;" : "=r"(lo) : "f"(lf));
    hi = h;
}

// d += A(16x8 tf32) * B(8x8 tf32), fp32 accum
__device__ __forceinline__ void mma8(float* d, const uint32_t* a, const uint32_t* b) {
    asm volatile(
        "mma.sync.aligned.m16n8k8.row.col.f32.tf32.tf32.f32 "
        "{%0,%1,%2,%3},{%4,%5,%6,%7},{%8,%9},{%0,%1,%2,%3};"
        : "+f"(d[0]), "+f"(d[1]), "+f"(d[2]), "+f"(d[3])
        : "r"(a[0]), "r"(a[1]), "r"(a[2]), "r"(a[3]), "r"(b[0]), "r"(b[1]));
}

// ---------------- HMMA tf32x3 GEMM: C[M,N] = act([A0|A1][M,K] * W[N,K]^T + b) ----------------
// 128x128 CTA tile, BK=32, 8 warps (4m x 2n), warp tile 32x64.
// smem (uint32): sA[2buf][2part][128][36], sB same. 147456 bytes.
__global__ void __launch_bounds__(256, 1) mma_gemm(
    const float* __restrict__ A0, int W0,
    const float* __restrict__ A1, int W1,
    const float* __restrict__ W, const float* __restrict__ bias,
    float* __restrict__ C, int N, int K, int relu)
{
    extern __shared__ uint32_t sm[];
    uint32_t* sA = sm;             // [buf][part][m][36]
    uint32_t* sB = sm + 18432;

    const int tid = threadIdx.x, lane = tid & 31, wid = tid >> 5;
    const int m0 = blockIdx.y * 128, bn = blockIdx.x * 128;
    const int wm0 = (wid >> 1) * 32, wn0 = (wid & 1) * 64;
    const int klane = tid & 31;
    const int r = lane >> 2, kq = lane & 3;
    const int NC = (K + 31) >> 5;

    float acc[2][8][4];
    #pragma unroll
    for (int i = 0; i < 2; i++)
        #pragma unroll
        for (int j = 0; j < 8; j++)
            #pragma unroll
            for (int e = 0; e < 4; e++) acc[i][j][e] = 0.f;

    float av[16], bv[16];

    auto prefetch = [&](int c) {
        const int kg = c * 32 + klane;
        const bool kok = kg < K;
        #pragma unroll
        for (int it = 0; it < 16; it++) {
            const int m = it * 8 + wid;
            float a = 0.f, b = 0.f;
            if (kok) {
                a = (kg < W0) ? A0[(size_t)(m0 + m) * W0 + kg]
                              : A1[(size_t)(m0 + m) * W1 + (kg - W0)];
                const int n = bn + m;
                if (n < N) b = W[(size_t)n * K + kg];
            }
            av[it] = a; bv[it] = b;
        }
    };
    auto store = [&](int b) {
        uint32_t* dA = sA + b * 9216;
        uint32_t* dB = sB + b * 9216;
        #pragma unroll
        for (int it = 0; it < 16; it++) {
            const int m = it * 8 + wid;
            uint32_t hi, lo;
            split_tf32(av[it], hi, lo);
            dA[m * 36 + klane] = hi; dA[4608 + m * 36 + klane] = lo;
            split_tf32(bv[it], hi, lo);
            dB[m * 36 + klane] = hi; dB[4608 + m * 36 + klane] = lo;
        }
    };
    auto compute = [&](int b) {
        const uint32_t* Ah = sA + b * 9216;
        const uint32_t* Al = Ah + 4608;
        const uint32_t* Bh = sB + b * 9216;
        const uint32_t* Bl = Bh + 4608;
        #pragma unroll
        for (int ks = 0; ks < 4; ks++) {
            const int k0 = ks * 8;
            uint32_t ah[2][4], al[2][4], bh[8][2], bl[8][2];
            #pragma unroll
            for (int mt = 0; mt < 2; mt++) {
                const int mb = wm0 + mt * 16;
                ah[mt][0] = Ah[(mb + r) * 36 + k0 + kq];
                ah[mt][1] = Ah[(mb + r + 8) * 36 + k0 + kq];
                ah[mt][2] = Ah[(mb + r) * 36 + k0 + kq + 4];
                ah[mt][3] = Ah[(mb + r + 8) * 36 + k0 + kq + 4];
                al[mt][0] = Al[(mb + r) * 36 + k0 + kq];
                al[mt][1] = Al[(mb + r + 8) * 36 + k0 + kq];
                al[mt][2] = Al[(mb + r) * 36 + k0 + kq + 4];
                al[mt][3] = Al[(mb + r + 8) * 36 + k0 + kq + 4];
            }
            #pragma unroll
            for (int nt = 0; nt < 8; nt++) {
                const int nb = wn0 + nt * 8;
                bh[nt][0] = Bh[(nb + r) * 36 + k0 + kq];
                bh[nt][1] = Bh[(nb + r) * 36 + k0 + kq + 4];
                bl[nt][0] = Bl[(nb + r) * 36 + k0 + kq];
                bl[nt][1] = Bl[(nb + r) * 36 + k0 + kq + 4];
            }
            #pragma unroll
            for (int mt = 0; mt < 2; mt++)
                #pragma unroll
                for (int nt = 0; nt < 8; nt++) {
                    mma8(acc[mt][nt], ah[mt], bh[nt]);
                    mma8(acc[mt][nt], ah[mt], bl[nt]);
                    mma8(acc[mt][nt], al[mt], bh[nt]);
                }
        }
    };

    prefetch(0); store(0); __syncthreads();
    for (int c = 0; c < NC; c++) {
        const int b = c & 1;
        if (c + 1 < NC) prefetch(c + 1);
        compute(b);
        if (c + 1 < NC) store(b ^ 1);
        __syncthreads();
    }

    // epilogue: direct global stores with bias + relu
    #pragma unroll
    for (int mt = 0; mt < 2; mt++) {
        const int rbase = m0 + wm0 + mt * 16 + r;
        #pragma unroll
        for (int q = 0; q < 2; q++) {
            const int row = rbase + q * 8;
            #pragma unroll
            for (int nt = 0; nt < 8; nt++) {
                const int n = bn + wn0 + nt * 8 + 2 * kq;
                float v0 = acc[mt][nt][q * 2 + 0];
                float v1 = acc[mt][nt][q * 2 + 1];
                if (n < N) {
                    float o = v0 + bias[n];
                    if (relu) o = fmaxf(o, 0.f);
                    C[(size_t)row * N + n] = o;
                }
                if (n + 1 < N) {
                    float o = v1 + bias[n + 1];
                    if (relu) o = fmaxf(o, 0.f);
                    C[(size_t)row * N + n + 1] = o;
                }
            }
        }
    }
}

// ---------------- VQ argmin via HMMA: 128 rows/CTA, 8 code-tiles of 128, K=64 ----------------
// score = esq[k] - 2*mu.e_k ; ties -> lowest index (matches argmax-first).
// Warp pair (2w, 2w+1) shares rows, splits codes -> must merge via smem.
__global__ void __launch_bounds__(256, 1) vq_mma()
{
    extern __shared__ uint32_t sm[];
    uint32_t* sMu = sm;             // [2ch][2part][128][36] = 18432
    uint32_t* sE  = sm + 18432;     // [2ch][2part][128][36] = 18432
    float* esq_s  = (float*)(sm + 36864);   // 1024

    __shared__ float sbest[8][2][2][8];
    __shared__ int   sidx[8][2][2][8];

    const int tid = threadIdx.x, lane = tid & 31, wid = tid >> 5;
    const int m0 = blockIdx.x * 128;
    const int wm0 = (wid >> 1) * 32, wn0 = (wid & 1) * 64;
    const int r = lane >> 2, kq = lane & 3;

    const int kl = tid & 63, ch = kl >> 5, kk = kl & 31;

    // load mu (split) + esq
    #pragma unroll
    for (int it = 0; it < 32; it++) {
        const int m = it * 4 + (tid >> 6);
        const float v = g_mu[(size_t)(m0 + m) * LDIM + kl];
        uint32_t hi, lo; split_tf32(v, hi, lo);
        sMu[ch * 9216 + m * 36 + kk] = hi;
        sMu[ch * 9216 + 4608 + m * 36 + kk] = lo;
    }
    for (int i = tid; i < KCODE; i += 256) esq_s[i] = g_esq[i];

    float best[2][2];
    int   bidx[2][2];
    #pragma unroll
    for (int i = 0; i < 2; i++)
        #pragma unroll
        for (int j = 0; j < 2; j++) { best[i][j] = 3.4e38f; bidx[i][j] = 0; }

    float ev[32];
    for (int ct = 0; ct < 8; ct++) {
        // prefetch code tile
        #pragma unroll
        for (int it = 0; it < 32; it++) {
            const int n = it * 4 + (tid >> 6);
            ev[it] = g_et[(size_t)(ct * 128 + n) * LDIM + kl];
        }
        __syncthreads();   // prior compute done reading sE (also covers mu/esq on ct=0)
        #pragma unroll
        for (int it = 0; it < 32; it++) {
            const int n = it * 4 + (tid >> 6);
            uint32_t hi, lo; split_tf32(ev[it], hi, lo);
            sE[ch * 9216 + n * 36 + kk] = hi;
            sE[ch * 9216 + 4608 + n * 36 + kk] = lo;
        }
        __syncthreads();

        float acc[2][8][4];
        #pragma unroll
        for (int i = 0; i < 2; i++)
            #pragma unroll
            for (int j = 0; j < 8; j++)
                #pragma unroll
                for (int e = 0; e < 4; e++) acc[i][j][e] = 0.f;

        #pragma unroll
        for (int cc = 0; cc < 2; cc++) {
            const uint32_t* Ah = sMu + cc * 9216;
            const uint32_t* Al = Ah + 4608;
            const uint32_t* Bh = sE + cc * 9216;
            const uint32_t* Bl = Bh + 4608;
            #pragma unroll
            for (int ks = 0; ks < 4; ks++) {
                const int k0 = ks * 8;
                uint32_t ah[2][4], al[2][4], bh[8][2], bl[8][2];
                #pragma unroll
                for (int mt = 0; mt < 2; mt++) {
                    const int mb = wm0 + mt * 16;
                    ah[mt][0] = Ah[(mb + r) * 36 + k0 + kq];
                    ah[mt][1] = Ah[(mb + r + 8) * 36 + k0 + kq];
                    ah[mt][2] = Ah[(mb + r) * 36 + k0 + kq + 4];
                    ah[mt][3] = Ah[(mb + r + 8) * 36 + k0 + kq + 4];
                    al[mt][0] = Al[(mb + r) * 36 + k0 + kq];
                    al[mt][1] = Al[(mb + r + 8) * 36 + k0 + kq];
                    al[mt][2] = Al[(mb + r) * 36 + k0 + kq + 4];
                    al[mt][3] = Al[(mb + r + 8) * 36 + k0 + kq + 4];
                }
                #pragma unroll
                for (int nt = 0; nt < 8; nt++) {
                    const int nb = wn0 + nt * 8;
                    bh[nt][0] = Bh[(nb + r) * 36 + k0 + kq];
                    bh[nt][1] = Bh[(nb + r) * 36 + k0 + kq + 4];
                    bl[nt][0] = Bl[(nb + r) * 36 + k0 + kq];
                    bl[nt][1] = Bl[(nb + r) * 36 + k0 + kq + 4];
                }
                #pragma unroll
                for (int mt = 0; mt < 2; mt++)
                    #pragma unroll
                    for (int nt = 0; nt < 8; nt++) {
                        mma8(acc[mt][nt], ah[mt], bh[nt]);
                        mma8(acc[mt][nt], ah[mt], bl[nt]);
                        mma8(acc[mt][nt], al[mt], bh[nt]);
                    }
            }
        }

        // score + argmin update (ascending code order; strict < keeps first min)
        #pragma unroll
        for (int mt = 0; mt < 2; mt++)
            #pragma unroll
            for (int q = 0; q < 2; q++)
                #pragma unroll
                for (int nt = 0; nt < 8; nt++)
                    #pragma unroll
                    for (int e = 0; e < 2; e++) {
                        const int code = ct * 128 + wn0 + nt * 8 + 2 * kq + e;
                        const float sc = esq_s[code] - 2.f * acc[mt][nt][q * 2 + e];
                        if (sc < best[mt][q]) { best[mt][q] = sc; bidx[mt][q] = code; }
                    }
        __syncthreads();
    }

    // 1) reduce across the 4 lanes of each quad (same rows, different code subsets)
    #pragma unroll
    for (int mt = 0; mt < 2; mt++)
        #pragma unroll
        for (int q = 0; q < 2; q++) {
            float b = best[mt][q]; int ix = bidx[mt][q];
            #pragma unroll
            for (int s = 1; s <= 2; s <<= 1) {
                const float ob = __shfl_xor_sync(0xffffffffu, b, s);
                const int   oi = __shfl_xor_sync(0xffffffffu, ix, s);
                if (ob < b || (ob == b && oi < ix)) { b = ob; ix = oi; }
            }
            if (kq == 0) { sbest[wid][mt][q][r] = b; sidx[wid][mt][q][r] = ix; }
        }
    __syncthreads();

    // 2) merge warp pair (codes split by wn0) and write final index
    if ((wid & 1) == 0 && kq == 0) {
        #pragma unroll
        for (int mt = 0; mt < 2; mt++)
            #pragma unroll
            for (int q = 0; q < 2; q++) {
                float b0 = sbest[wid][mt][q][r];     int i0 = sidx[wid][mt][q][r];
                float b1 = sbest[wid + 1][mt][q][r]; int i1 = sidx[wid + 1][mt][q][r];
                int ix = (b1 < b0 || (b1 == b0 && i1 < i0)) ? i1 : i0;
                g_idx[m0 + wm0 + mt * 16 + r + q * 8] = ix;
            }
    }
}

// ---------------- small prep / VQ-stat kernels ----------------
__global__ void esq_kernel(const float* __restrict__ embed) {
    int k = blockIdx.x * blockDim.x + threadIdx.x;
    if (k < KCODE) {
        float s = 0.f;
        #pragma unroll 8
        for (int l = 0; l < LDIM; l++) { float e = embed[l * KCODE + k]; s += e * e; }
        g_esq[k] = s;
    }
}
__global__ void embed_t_kernel(const float* __restrict__ embed) {
    int i = blockIdx.x * blockDim.x + threadIdx.x;
    if (i < LDIM * KCODE) {
        int l = i >> 10, c = i & (KCODE - 1);
        g_et[c * LDIM + l] = embed[i];
    }
}
__global__ void zero_counts_kernel() {
    int i = blockIdx.x * blockDim.x + threadIdx.x;
    if (i < KCODE) g_counts[i] = 0;
}

__global__ void __launch_bounds__(256) gather_loss_kernel(const float* __restrict__ embed) {
    __shared__ float ps[8];
    const int w = threadIdx.x >> 5, lane = threadIdx.x & 31;
    const int row = blockIdx.x * 8 + w;
    const int idx = g_idx[row];
    float s = 0.f;
    #pragma unroll
    for (int h = 0; h < 2; h++) {
        int l = lane + 32 * h;
        float e = embed[l * KCODE + idx];
        g_q[(size_t)row * LDIM + l] = e;
        float d = e - g_mu[(size_t)row * LDIM + l];
        s += d * d;
    }
    #pragma unroll
    for (int off = 16; off; off >>= 1) s += __shfl_down_sync(0xffffffffu, s, off);
    if (lane == 0) { ps[w] = s; atomicAdd(&g_counts[idx], 1); }
    __syncthreads();
    if (threadIdx.x == 0) {
        float t = 0.f;
        #pragma unroll
        for (int i = 0; i < 8; i++) t += ps[i];
        g_partials[blockIdx.x] = t;
    }
}

__global__ void __launch_bounds__(256) finalize_kernel(float* __restrict__ out) {
    __shared__ float red[256];
    const int t = threadIdx.x;
    float s = 0.f;
    for (int i = t; i < BB / 8; i += 256) s += g_partials[i];
    red[t] = s;
    for (int st = 128; st > 0; st >>= 1) { __syncthreads(); if (t < st) red[t] += red[t + st]; }
    __syncthreads();
    float loss = red[0] / (float)((size_t)BB * LDIM);
    __syncthreads();
    float e = 0.f;
    for (int k = t; k < KCODE; k += 256) {
        float p = (float)g_counts[k] / (float)BB;
        e += p * logf(p + 1e-10f);
    }
    red[t] = e;
    for (int st = 128; st > 0; st >>= 1) { __syncthreads(); if (t < st) red[t] += red[t + st]; }
    __syncthreads();
    if (t == 0) {
        out[(size_t)BB * FDIM] = loss;
        out[(size_t)BB * FDIM + 1] = expf(-red[0]);
    }
}

// ---------------- host launcher ----------------
extern "C" void kernel_launch(void* const* d_in, const int* in_sizes, int n_in,
                              void* d_out, int out_size)
{
    const float* x     = (const float*)d_in[0];
    const float* c     = (const float*)d_in[1];
    const float* fc1_w = (const float*)d_in[2];
    const float* fc1_b = (const float*)d_in[3];
    const float* fc2_w = (const float*)d_in[4];
    const float* fc2_b = (const float*)d_in[5];
    const float* fc3_w = (const float*)d_in[6];
    const float* fc3_b = (const float*)d_in[7];
    const float* mu_w  = (const float*)d_in[8];
    const float* mu_b  = (const float*)d_in[9];
    const float* fc4_w = (const float*)d_in[10];
    const float* fc4_b = (const float*)d_in[11];
    const float* fc5_w = (const float*)d_in[12];
    const float* fc5_b = (const float*)d_in[13];
    const float* fc6_w = (const float*)d_in[14];
    const float* fc6_b = (const float*)d_in[15];
    const float* out_w = (const float*)d_in[16];
    const float* out_b = (const float*)d_in[17];
    const float* embed = (const float*)d_in[18];
    float* out = (float*)d_out;

    float *h1, *h2, *mu, *q;
    cudaGetSymbolAddress((void**)&h1, g_h1);
    cudaGetSymbolAddress((void**)&h2, g_h2);
    cudaGetSymbolAddress((void**)&mu, g_mu);
    cudaGetSymbolAddress((void**)&q,  g_q);

    const int GEMM_SMEM = 2 * 18432 * 4;              // 147456 B
    const int VQ_SMEM   = (2 * 18432 + 1024) * 4;     // 151552 B
    cudaFuncSetAttribute(mma_gemm, cudaFuncAttributeMaxDynamicSharedMemorySize, GEMM_SMEM);
    cudaFuncSetAttribute(vq_mma,   cudaFuncAttributeMaxDynamicSharedMemorySize, VQ_SMEM);

    const dim3 blk(256);
    const dim3 g256(2, BB / 128);
    const dim3 g64(1, BB / 128);
    const dim3 g267(3, BB / 128);

    // prep
    esq_kernel<<<4, 256>>>(embed);
    embed_t_kernel<<<(LDIM * KCODE + 255) / 256, 256>>>(embed);
    zero_counts_kernel<<<4, 256>>>();

    // encoder
    mma_gemm<<<g256, blk, GEMM_SMEM>>>(x, FDIM, c, FDIM, fc1_w, fc1_b, h1, HDIM, 2 * FDIM, 1);
    mma_gemm<<<g256, blk, GEMM_SMEM>>>(h1, HDIM, nullptr, 0, fc2_w, fc2_b, h2, HDIM, HDIM, 1);
    mma_gemm<<<g256, blk, GEMM_SMEM>>>(h2, HDIM, nullptr, 0, fc3_w, fc3_b, h1, HDIM, HDIM, 1);
    mma_gemm<<<g64,  blk, GEMM_SMEM>>>(h1, HDIM, nullptr, 0, mu_w, mu_b, mu, LDIM, HDIM, 0);

    // vector quantizer
    vq_mma<<<BB / 128, blk, VQ_SMEM>>>();
    gather_loss_kernel<<<BB / 8, 256>>>(embed);

    // decoder
    mma_gemm<<<g256, blk, GEMM_SMEM>>>(q, LDIM, c, FDIM, fc4_w, fc4_b, h2, HDIM, LDIM + FDIM, 1);
    mma_gemm<<<g256, blk, GEMM_SMEM>>>(h2, HDIM, nullptr, 0, fc5_w, fc5_b, h1, HDIM, HDIM, 1);
    mma_gemm<<<g256, blk, GEMM_SMEM>>>(h1, HDIM, nullptr, 0, fc6_w, fc6_b, h2, HDIM, HDIM, 1);
    mma_gemm<<<g267, blk, GEMM_SMEM>>>(h2, HDIM, nullptr, 0, out_w, out_b, out, FDIM, HDIM, 0);

    // scalars
    finalize_kernel<<<1, 256>>>(out);
}

// round 5
// speedup vs baseline: 1.9484x; 1.1462x over previous
#include <cuda_runtime.h>
#include <cstdint>
#include <math.h>

#define BB 65536
#define FDIM 267
#define HDIM 256
#define LDIM 64
#define KCODE 1024

// ---------------- scratch (device globals) ----------------
__device__ float g_h1[BB * HDIM];
__device__ float g_h2[BB * HDIM];
__device__ float g_mu[BB * LDIM];
__device__ float g_q[BB * LDIM];
__device__ int   g_idx[BB];
__device__ float g_esq[KCODE];
__device__ int   g_counts[KCODE];
__device__ float g_partials[BB / 8];
__device__ float g_et[KCODE * LDIM];   // transposed codebook [code][l]

// ---------------- helpers ----------------
// Dekker-style split: hi = a with low 13 mantissa bits zeroed (exact tf32-representable),
// lo = a - hi (exact). HMMA reads top 19 bits of each fp32 operand -> lo tail truncates.
__device__ __forceinline__ void msplit(float a, uint32_t& hi, uint32_t& lo) {
    uint32_t h = __float_as_uint(a) & 0xFFFFE000u;
    hi = h;
    lo = __float_as_uint(a - __uint_as_float(h));
}

// column permutation: fragment pair (k0+kq, k0+kq+4) becomes contiguous
__device__ __forceinline__ int kperm(int k) {
    return ((k >> 3) << 3) | ((k & 3) << 1) | ((k >> 2) & 1);
}

// d += A(16x8 tf32) * B(8x8 tf32), fp32 accum
__device__ __forceinline__ void mma8(float* d, const uint32_t* a, const uint32_t* b) {
    asm volatile(
        "mma.sync.aligned.m16n8k8.row.col.f32.tf32.tf32.f32 "
        "{%0,%1,%2,%3},{%4,%5,%6,%7},{%8,%9},{%0,%1,%2,%3};"
        : "+f"(d[0]), "+f"(d[1]), "+f"(d[2]), "+f"(d[3])
        : "r"(a[0]), "r"(a[1]), "r"(a[2]), "r"(a[3]), "r"(b[0]), "r"(b[1]));
}

// ---------------- HMMA tf32x3 GEMM: C[M,N] = act([A0|A1][M,K] * W[N,K]^T + b) ----------------
// 128x128 CTA tile, BK=32, 16 warps (4m x 4n), warp tile 32x32, raw fp32 smem + register split.
// smem floats: sA[2][128][36], sB[2][128][36] = 73728 bytes.
__global__ void __launch_bounds__(512, 1) mma_gemm(
    const float* __restrict__ A0, int W0,
    const float* __restrict__ A1, int W1,
    const float* __restrict__ W, const float* __restrict__ bias,
    float* __restrict__ C, int N, int K, int relu)
{
    extern __shared__ float sm[];
    float* sAb = sm;            // [buf][128][36]
    float* sBb = sm + 9216;

    const int tid = threadIdx.x, lane = tid & 31, wid = tid >> 5;
    const int m0 = blockIdx.y * 128, bn = blockIdx.x * 128;
    const int wm0 = (wid >> 2) * 32, wn0 = (wid & 3) * 32;
    const int r = lane >> 2, kq = lane & 3;
    const int NC = (K + 31) >> 5;
    const int kcol = kperm(lane);

    float acc[2][4][4];
    #pragma unroll
    for (int i = 0; i < 2; i++)
        #pragma unroll
        for (int j = 0; j < 4; j++)
            #pragma unroll
            for (int e = 0; e < 4; e++) acc[i][j][e] = 0.f;

    float av[8], bv[8];

    auto prefetch = [&](int c) {
        const int kg = c * 32 + lane;
        const bool kok = kg < K;
        #pragma unroll
        for (int it = 0; it < 8; it++) {
            const int m = it * 16 + wid;
            float a = 0.f, b = 0.f;
            if (kok) {
                a = (kg < W0) ? A0[(size_t)(m0 + m) * W0 + kg]
                              : A1[(size_t)(m0 + m) * W1 + (kg - W0)];
                const int n = bn + m;
                if (n < N) b = W[(size_t)n * K + kg];
            }
            av[it] = a; bv[it] = b;
        }
    };
    auto store = [&](int b) {
        float* dA = sAb + b * 4608;
        float* dB = sBb + b * 4608;
        #pragma unroll
        for (int it = 0; it < 8; it++) {
            const int row = it * 16 + wid;
            dA[row * 36 + kcol] = av[it];
            dB[row * 36 + kcol] = bv[it];
        }
    };
    auto compute = [&](int b) {
        const float* fA = sAb + b * 4608;
        const float* fB = sBb + b * 4608;
        #pragma unroll
        for (int ks = 0; ks < 4; ks++) {
            const int co = ks * 8 + kq * 2;
            float2 ar0[2], ar1[2], br[4];
            #pragma unroll
            for (int mt = 0; mt < 2; mt++) {
                const int mb = wm0 + mt * 16;
                ar0[mt] = *(const float2*)&fA[(mb + r) * 36 + co];
                ar1[mt] = *(const float2*)&fA[(mb + r + 8) * 36 + co];
            }
            #pragma unroll
            for (int nt = 0; nt < 4; nt++)
                br[nt] = *(const float2*)&fB[(wn0 + nt * 8 + r) * 36 + co];

            uint32_t ah[2][4], al[2][4], bh[4][2], bl[4][2];
            #pragma unroll
            for (int mt = 0; mt < 2; mt++) {
                msplit(ar0[mt].x, ah[mt][0], al[mt][0]);
                msplit(ar1[mt].x, ah[mt][1], al[mt][1]);
                msplit(ar0[mt].y, ah[mt][2], al[mt][2]);
                msplit(ar1[mt].y, ah[mt][3], al[mt][3]);
            }
            #pragma unroll
            for (int nt = 0; nt < 4; nt++) {
                msplit(br[nt].x, bh[nt][0], bl[nt][0]);
                msplit(br[nt].y, bh[nt][1], bl[nt][1]);
            }
            #pragma unroll
            for (int mt = 0; mt < 2; mt++)
                #pragma unroll
                for (int nt = 0; nt < 4; nt++) {
                    mma8(acc[mt][nt], ah[mt], bh[nt]);
                    mma8(acc[mt][nt], ah[mt], bl[nt]);
                    mma8(acc[mt][nt], al[mt], bh[nt]);
                }
        }
    };

    prefetch(0); store(0); __syncthreads();
    for (int c = 0; c < NC; c++) {
        const int b = c & 1;
        if (c + 1 < NC) prefetch(c + 1);
        compute(b);
        if (c + 1 < NC) store(b ^ 1);
        __syncthreads();
    }

    // epilogue: bias + relu, float2 stores when aligned
    const bool evenN = (N & 1) == 0;
    #pragma unroll
    for (int mt = 0; mt < 2; mt++) {
        #pragma unroll
        for (int q = 0; q < 2; q++) {
            const int row = m0 + wm0 + mt * 16 + q * 8 + r;
            #pragma unroll
            for (int nt = 0; nt < 4; nt++) {
                const int n = bn + wn0 + nt * 8 + 2 * kq;
                float v0 = acc[mt][nt][q * 2 + 0];
                float v1 = acc[mt][nt][q * 2 + 1];
                if (n + 1 < N) {
                    float o0 = v0 + bias[n];
                    float o1 = v1 + bias[n + 1];
                    if (relu) { o0 = fmaxf(o0, 0.f); o1 = fmaxf(o1, 0.f); }
                    if (evenN) {
                        float2 p; p.x = o0; p.y = o1;
                        *(float2*)&C[(size_t)row * N + n] = p;
                    } else {
                        C[(size_t)row * N + n] = o0;
                        C[(size_t)row * N + n + 1] = o1;
                    }
                } else if (n < N) {
                    float o0 = v0 + bias[n];
                    if (relu) o0 = fmaxf(o0, 0.f);
                    C[(size_t)row * N + n] = o0;
                }
            }
        }
    }
}

// ---------------- VQ argmin via HMMA: 128 rows/CTA, 8 code-tiles of 128, K=64 ----------------
// score = esq[k] - 2*mu.e_k ; ties -> lowest index. 256 threads, 8 warps (4m x 2n).
// raw fp32 smem + register split; reduction logic identical to R4 (proven).
__global__ void __launch_bounds__(256, 1) vq_mma()
{
    extern __shared__ float smf[];
    float* sMu = smf;               // [2ch][128][36] = 9216 floats
    float* sE  = smf + 9216;        // [2ch][128][36] = 9216 floats
    float* esq_s = smf + 18432;     // 1024 floats

    __shared__ float sbest[8][2][2][8];
    __shared__ int   sidx[8][2][2][8];

    const int tid = threadIdx.x, lane = tid & 31, wid = tid >> 5;
    const int m0 = blockIdx.x * 128;
    const int wm0 = (wid >> 1) * 32, wn0 = (wid & 1) * 64;
    const int r = lane >> 2, kq = lane & 3;

    const int kl = tid & 63, ch = kl >> 5, kk = kl & 31;
    const int kcol = kperm(kk);

    // load mu (raw) + esq
    #pragma unroll
    for (int it = 0; it < 32; it++) {
        const int m = it * 4 + (tid >> 6);
        sMu[ch * 4608 + m * 36 + kcol] = g_mu[(size_t)(m0 + m) * LDIM + kl];
    }
    for (int i = tid; i < KCODE; i += 256) esq_s[i] = g_esq[i];

    float best[2][2];
    int   bidx[2][2];
    #pragma unroll
    for (int i = 0; i < 2; i++)
        #pragma unroll
        for (int j = 0; j < 2; j++) { best[i][j] = 3.4e38f; bidx[i][j] = 0; }

    float ev[32];
    for (int ct = 0; ct < 8; ct++) {
        // prefetch code tile
        #pragma unroll
        for (int it = 0; it < 32; it++) {
            const int n = it * 4 + (tid >> 6);
            ev[it] = g_et[(size_t)(ct * 128 + n) * LDIM + kl];
        }
        __syncthreads();   // prior compute done reading sE (also covers mu/esq on ct=0)
        #pragma unroll
        for (int it = 0; it < 32; it++) {
            const int n = it * 4 + (tid >> 6);
            sE[ch * 4608 + n * 36 + kcol] = ev[it];
        }
        __syncthreads();

        float acc[2][8][4];
        #pragma unroll
        for (int i = 0; i < 2; i++)
            #pragma unroll
            for (int j = 0; j < 8; j++)
                #pragma unroll
                for (int e = 0; e < 4; e++) acc[i][j][e] = 0.f;

        #pragma unroll
        for (int cc = 0; cc < 2; cc++) {
            const float* Ab = sMu + cc * 4608;
            const float* Bb = sE + cc * 4608;
            #pragma unroll
            for (int ks = 0; ks < 4; ks++) {
                const int co = ks * 8 + kq * 2;
                float2 ar0[2], ar1[2], br[8];
                #pragma unroll
                for (int mt = 0; mt < 2; mt++) {
                    const int mb = wm0 + mt * 16;
                    ar0[mt] = *(const float2*)&Ab[(mb + r) * 36 + co];
                    ar1[mt] = *(const float2*)&Ab[(mb + r + 8) * 36 + co];
                }
                #pragma unroll
                for (int nt = 0; nt < 8; nt++)
                    br[nt] = *(const float2*)&Bb[(wn0 + nt * 8 + r) * 36 + co];

                uint32_t ah[2][4], al[2][4], bh[8][2], bl[8][2];
                #pragma unroll
                for (int mt = 0; mt < 2; mt++) {
                    msplit(ar0[mt].x, ah[mt][0], al[mt][0]);
                    msplit(ar1[mt].x, ah[mt][1], al[mt][1]);
                    msplit(ar0[mt].y, ah[mt][2], al[mt][2]);
                    msplit(ar1[mt].y, ah[mt][3], al[mt][3]);
                }
                #pragma unroll
                for (int nt = 0; nt < 8; nt++) {
                    msplit(br[nt].x, bh[nt][0], bl[nt][0]);
                    msplit(br[nt].y, bh[nt][1], bl[nt][1]);
                }
                #pragma unroll
                for (int mt = 0; mt < 2; mt++)
                    #pragma unroll
                    for (int nt = 0; nt < 8; nt++) {
                        mma8(acc[mt][nt], ah[mt], bh[nt]);
                        mma8(acc[mt][nt], ah[mt], bl[nt]);
                        mma8(acc[mt][nt], al[mt], bh[nt]);
                    }
            }
        }

        // score + argmin update (ascending code order; strict < keeps first min)
        #pragma unroll
        for (int mt = 0; mt < 2; mt++)
            #pragma unroll
            for (int q = 0; q < 2; q++)
                #pragma unroll
                for (int nt = 0; nt < 8; nt++)
                    #pragma unroll
                    for (int e = 0; e < 2; e++) {
                        const int code = ct * 128 + wn0 + nt * 8 + 2 * kq + e;
                        const float sc = esq_s[code] - 2.f * acc[mt][nt][q * 2 + e];
                        if (sc < best[mt][q]) { best[mt][q] = sc; bidx[mt][q] = code; }
                    }
        __syncthreads();
    }

    // 1) reduce across the 4 lanes of each quad (same rows, different code subsets)
    #pragma unroll
    for (int mt = 0; mt < 2; mt++)
        #pragma unroll
        for (int q = 0; q < 2; q++) {
            float b = best[mt][q]; int ix = bidx[mt][q];
            #pragma unroll
            for (int s = 1; s <= 2; s <<= 1) {
                const float ob = __shfl_xor_sync(0xffffffffu, b, s);
                const int   oi = __shfl_xor_sync(0xffffffffu, ix, s);
                if (ob < b || (ob == b && oi < ix)) { b = ob; ix = oi; }
            }
            if (kq == 0) { sbest[wid][mt][q][r] = b; sidx[wid][mt][q][r] = ix; }
        }
    __syncthreads();

    // 2) merge warp pair (codes split by wn0) and write final index
    if ((wid & 1) == 0 && kq == 0) {
        #pragma unroll
        for (int mt = 0; mt < 2; mt++)
            #pragma unroll
            for (int q = 0; q < 2; q++) {
                float b0 = sbest[wid][mt][q][r];     int i0 = sidx[wid][mt][q][r];
                float b1 = sbest[wid + 1][mt][q][r]; int i1 = sidx[wid + 1][mt][q][r];
                int ix = (b1 < b0 || (b1 == b0 && i1 < i0)) ? i1 : i0;
                g_idx[m0 + wm0 + mt * 16 + r + q * 8] = ix;
            }
    }
}

// ---------------- small prep / VQ-stat kernels ----------------
__global__ void esq_kernel(const float* __restrict__ embed) {
    int k = blockIdx.x * blockDim.x + threadIdx.x;
    if (k < KCODE) {
        float s = 0.f;
        #pragma unroll 8
        for (int l = 0; l < LDIM; l++) { float e = embed[l * KCODE + k]; s += e * e; }
        g_esq[k] = s;
    }
}
__global__ void embed_t_kernel(const float* __restrict__ embed) {
    int i = blockIdx.x * blockDim.x + threadIdx.x;
    if (i < LDIM * KCODE) {
        int l = i >> 10, c = i & (KCODE - 1);
        g_et[c * LDIM + l] = embed[i];
    }
}
__global__ void zero_counts_kernel() {
    int i = blockIdx.x * blockDim.x + threadIdx.x;
    if (i < KCODE) g_counts[i] = 0;
}

__global__ void __launch_bounds__(256) gather_loss_kernel(const float* __restrict__ embed) {
    __shared__ float ps[8];
    const int w = threadIdx.x >> 5, lane = threadIdx.x & 31;
    const int row = blockIdx.x * 8 + w;
    const int idx = g_idx[row];
    float s = 0.f;
    #pragma unroll
    for (int h = 0; h < 2; h++) {
        int l = lane + 32 * h;
        float e = embed[l * KCODE + idx];
        g_q[(size_t)row * LDIM + l] = e;
        float d = e - g_mu[(size_t)row * LDIM + l];
        s += d * d;
    }
    #pragma unroll
    for (int off = 16; off; off >>= 1) s += __shfl_down_sync(0xffffffffu, s, off);
    if (lane == 0) { ps[w] = s; atomicAdd(&g_counts[idx], 1); }
    __syncthreads();
    if (threadIdx.x == 0) {
        float t = 0.f;
        #pragma unroll
        for (int i = 0; i < 8; i++) t += ps[i];
        g_partials[blockIdx.x] = t;
    }
}

__global__ void __launch_bounds__(256) finalize_kernel(float* __restrict__ out) {
    __shared__ float red[256];
    const int t = threadIdx.x;
    float s = 0.f;
    for (int i = t; i < BB / 8; i += 256) s += g_partials[i];
    red[t] = s;
    for (int st = 128; st > 0; st >>= 1) { __syncthreads(); if (t < st) red[t] += red[t + st]; }
    __syncthreads();
    float loss = red[0] / (float)((size_t)BB * LDIM);
    __syncthreads();
    float e = 0.f;
    for (int k = t; k < KCODE; k += 256) {
        float p = (float)g_counts[k] / (float)BB;
        e += p * logf(p + 1e-10f);
    }
    red[t] = e;
    for (int st = 128; st > 0; st >>= 1) { __syncthreads(); if (t < st) red[t] += red[t + st]; }
    __syncthreads();
    if (t == 0) {
        out[(size_t)BB * FDIM] = loss;
        out[(size_t)BB * FDIM + 1] = expf(-red[0]);
    }
}

// ---------------- host launcher ----------------
extern "C" void kernel_launch(void* const* d_in, const int* in_sizes, int n_in,
                              void* d_out, int out_size)
{
    const float* x     = (const float*)d_in[0];
    const float* c     = (const float*)d_in[1];
    const float* fc1_w = (const float*)d_in[2];
    const float* fc1_b = (const float*)d_in[3];
    const float* fc2_w = (const float*)d_in[4];
    const float* fc2_b = (const float*)d_in[5];
    const float* fc3_w = (const float*)d_in[6];
    const float* fc3_b = (const float*)d_in[7];
    const float* mu_w  = (const float*)d_in[8];
    const float* mu_b  = (const float*)d_in[9];
    const float* fc4_w = (const float*)d_in[10];
    const float* fc4_b = (const float*)d_in[11];
    const float* fc5_w = (const float*)d_in[12];
    const float* fc5_b = (const float*)d_in[13];
    const float* fc6_w = (const float*)d_in[14];
    const float* fc6_b = (const float*)d_in[15];
    const float* out_w = (const float*)d_in[16];
    const float* out_b = (const float*)d_in[17];
    const float* embed = (const float*)d_in[18];
    float* out = (float*)d_out;

    float *h1, *h2, *mu, *q;
    cudaGetSymbolAddress((void**)&h1, g_h1);
    cudaGetSymbolAddress((void**)&h2, g_h2);
    cudaGetSymbolAddress((void**)&mu, g_mu);
    cudaGetSymbolAddress((void**)&q,  g_q);

    const int GEMM_SMEM = 18432 * 4;              // 73728 B (2 bufs x (A+B) raw fp32)
    const int VQ_SMEM   = (18432 + 1024) * 4;     // 77824 B
    cudaFuncSetAttribute(mma_gemm, cudaFuncAttributeMaxDynamicSharedMemorySize, GEMM_SMEM);
    cudaFuncSetAttribute(vq_mma,   cudaFuncAttributeMaxDynamicSharedMemorySize, VQ_SMEM);

    const dim3 blk(512);
    const dim3 g256(2, BB / 128);
    const dim3 g64(1, BB / 128);
    const dim3 g267(3, BB / 128);

    // prep
    esq_kernel<<<4, 256>>>(embed);
    embed_t_kernel<<<(LDIM * KCODE + 255) / 256, 256>>>(embed);
    zero_counts_kernel<<<4, 256>>>();

    // encoder
    mma_gemm<<<g256, blk, GEMM_SMEM>>>(x, FDIM, c, FDIM, fc1_w, fc1_b, h1, HDIM, 2 * FDIM, 1);
    mma_gemm<<<g256, blk, GEMM_SMEM>>>(h1, HDIM, nullptr, 0, fc2_w, fc2_b, h2, HDIM, HDIM, 1);
    mma_gemm<<<g256, blk, GEMM_SMEM>>>(h2, HDIM, nullptr, 0, fc3_w, fc3_b, h1, HDIM, HDIM, 1);
    mma_gemm<<<g64,  blk, GEMM_SMEM>>>(h1, HDIM, nullptr, 0, mu_w, mu_b, mu, LDIM, HDIM, 0);

    // vector quantizer
    vq_mma<<<BB / 128, 256, VQ_SMEM>>>();
    gather_loss_kernel<<<BB / 8, 256>>>(embed);

    // decoder
    mma_gemm<<<g256, blk, GEMM_SMEM>>>(q, LDIM, c, FDIM, fc4_w, fc4_b, h2, HDIM, LDIM + FDIM, 1);
    mma_gemm<<<g256, blk, GEMM_SMEM>>>(h2, HDIM, nullptr, 0, fc5_w, fc5_b, h1, HDIM, HDIM, 1);
    mma_gemm<<<g256, blk, GEMM_SMEM>>>(h1, HDIM, nullptr, 0, fc6_w, fc6_b, h2, HDIM, HDIM, 1);
    mma_gemm<<<g267, blk, GEMM_SMEM>>>(h2, HDIM, nullptr, 0, out_w, out_b, out, FDIM, HDIM, 0);

    // scalars
    finalize_kernel<<<1, 256>>>(out);
}

// round 6
// speedup vs baseline: 3.0425x; 1.5615x over previous
#include <cuda_runtime.h>
#include <cstdint>
#include <math.h>

#define BB 65536
#define FDIM 267
#define HDIM 256
#define LDIM 64
#define KCODE 1024

// ---------------- scratch (device globals) ----------------
__device__ float g_h1[BB * HDIM];
__device__ float g_h2[BB * HDIM];
__device__ float g_mu[BB * LDIM];
__device__ float g_q[BB * LDIM];
__device__ int   g_idx[BB];
__device__ float g_esq[KCODE];
__device__ int   g_counts[KCODE];
__device__ float g_partials[BB / 8];
__device__ float g_et[KCODE * LDIM];   // transposed codebook [code][l]

// ---------------- helpers ----------------
// hi = a truncated to 10 mantissa bits (exactly fp16-representable in normal range)
__device__ __forceinline__ float hi32(float a) {
    return __uint_as_float(__float_as_uint(a) & 0xFFFFE000u);
}
// pack two floats as f16x2: x -> low half, y -> high half
__device__ __forceinline__ uint32_t packh(float x, float y) {
    uint32_t d;
    asm("cvt.rn.f16x2.f32 %0, %1, %2;" : "=r"(d) : "f"(y), "f"(x));
    return d;
}

// d += A(16x16 f16) * B(16x8 f16), fp32 accum
__device__ __forceinline__ void mma16(float* d, const uint32_t* a, const uint32_t* b) {
    asm volatile(
        "mma.sync.aligned.m16n8k16.row.col.f32.f16.f16.f32 "
        "{%0,%1,%2,%3},{%4,%5,%6,%7},{%8,%9},{%0,%1,%2,%3};"
        : "+f"(d[0]), "+f"(d[1]), "+f"(d[2]), "+f"(d[3])
        : "r"(a[0]), "r"(a[1]), "r"(a[2]), "r"(a[3]), "r"(b[0]), "r"(b[1]));
}

// ---------------- fp16x3 HMMA GEMM: C[M,N] = act([A0|A1][M,K] * W[N,K]^T + b) ----------------
// 128x128 CTA tile, BK=32, 16 warps (4m x 4n), warp tile 32x32.
// smem u32 tiles per buf: Ahi[128][20], Alo, Bhi, Blo (2560 u32 each); 2 bufs = 81920 B.
__global__ void __launch_bounds__(512, 1) mma_gemm(
    const float* __restrict__ A0, int W0,
    const float* __restrict__ A1, int W1,
    const float* __restrict__ W, const float* __restrict__ bias,
    float* __restrict__ C, int N, int K, int relu)
{
    extern __shared__ uint32_t smu[];

    const int tid = threadIdx.x, lane = tid & 31, wid = tid >> 5;
    const int m0 = blockIdx.y * 128, bn = blockIdx.x * 128;
    const int wm0 = (wid >> 2) * 32, wn0 = (wid & 3) * 32;
    const int r = lane >> 2, kq = lane & 3;
    const int NC = (K + 31) >> 5;
    const int prow = tid >> 4;     // 0..31 loader row
    const int pj   = tid & 15;     // u32 col (half2 pair index)
    const bool scalA = (A1 != nullptr);
    const bool scalB = (K & 1) != 0;

    float acc[2][4][4];
    #pragma unroll
    for (int i = 0; i < 2; i++)
        #pragma unroll
        for (int j = 0; j < 4; j++)
            #pragma unroll
            for (int e = 0; e < 4; e++) acc[i][j][e] = 0.f;

    float2 a2[4], b2[4];

    auto prefetch = [&](int c) {
        const int kg = c * 32 + 2 * pj;
        #pragma unroll
        for (int p = 0; p < 4; p++) {
            const int row = p * 32 + prow;
            float ax = 0.f, ay = 0.f, bx = 0.f, by = 0.f;
            if (scalA) {
                if (kg < K)
                    ax = (kg < W0) ? A0[(size_t)(m0 + row) * W0 + kg]
                                   : A1[(size_t)(m0 + row) * W1 + (kg - W0)];
                if (kg + 1 < K)
                    ay = (kg + 1 < W0) ? A0[(size_t)(m0 + row) * W0 + kg + 1]
                                       : A1[(size_t)(m0 + row) * W1 + (kg + 1 - W0)];
            } else if (kg < K) {
                float2 t = *(const float2*)&A0[(size_t)(m0 + row) * W0 + kg];
                ax = t.x; ay = t.y;
            }
            const int n = bn + row;
            if (n < N) {
                if (scalB) {
                    if (kg < K)     bx = W[(size_t)n * K + kg];
                    if (kg + 1 < K) by = W[(size_t)n * K + kg + 1];
                } else if (kg < K) {
                    float2 t = *(const float2*)&W[(size_t)n * K + kg];
                    bx = t.x; by = t.y;
                }
            }
            a2[p] = make_float2(ax, ay);
            b2[p] = make_float2(bx, by);
        }
    };
    auto store = [&](int b) {
        uint32_t* base = smu + b * 10240;
        #pragma unroll
        for (int p = 0; p < 4; p++) {
            const int o = (p * 32 + prow) * 20 + pj;
            float hx = hi32(a2[p].x), hy = hi32(a2[p].y);
            base[o]        = packh(hx, hy);
            base[2560 + o] = packh(a2[p].x - hx, a2[p].y - hy);
            hx = hi32(b2[p].x); hy = hi32(b2[p].y);
            base[5120 + o] = packh(hx, hy);
            base[7680 + o] = packh(b2[p].x - hx, b2[p].y - hy);
        }
    };
    auto compute = [&](int b) {
        const uint32_t* Ah = smu + b * 10240;
        const uint32_t* Al = Ah + 2560;
        const uint32_t* Bh = Ah + 5120;
        const uint32_t* Bl = Ah + 7680;
        #pragma unroll
        for (int ks = 0; ks < 2; ks++) {
            const int cb = ks * 8 + kq;
            uint32_t ah[2][4], al[2][4], bh[4][2], bl[4][2];
            #pragma unroll
            for (int mt = 0; mt < 2; mt++) {
                const int R0 = (wm0 + mt * 16 + r) * 20;
                const int R1 = R0 + 160;
                ah[mt][0] = Ah[R0 + cb]; ah[mt][1] = Ah[R1 + cb];
                ah[mt][2] = Ah[R0 + cb + 4]; ah[mt][3] = Ah[R1 + cb + 4];
                al[mt][0] = Al[R0 + cb]; al[mt][1] = Al[R1 + cb];
                al[mt][2] = Al[R0 + cb + 4]; al[mt][3] = Al[R1 + cb + 4];
            }
            #pragma unroll
            for (int nt = 0; nt < 4; nt++) {
                const int RB = (wn0 + nt * 8 + r) * 20;
                bh[nt][0] = Bh[RB + cb]; bh[nt][1] = Bh[RB + cb + 4];
                bl[nt][0] = Bl[RB + cb]; bl[nt][1] = Bl[RB + cb + 4];
            }
            #pragma unroll
            for (int mt = 0; mt < 2; mt++)
                #pragma unroll
                for (int nt = 0; nt < 4; nt++) {
                    mma16(acc[mt][nt], ah[mt], bh[nt]);
                    mma16(acc[mt][nt], ah[mt], bl[nt]);
                    mma16(acc[mt][nt], al[mt], bh[nt]);
                }
        }
    };

    prefetch(0); store(0); __syncthreads();
    for (int c = 0; c < NC; c++) {
        const int b = c & 1;
        if (c + 1 < NC) prefetch(c + 1);
        compute(b);
        if (c + 1 < NC) store(b ^ 1);
        __syncthreads();
    }

    // epilogue: bias + relu, float2 stores when aligned
    const bool evenN = (N & 1) == 0;
    #pragma unroll
    for (int mt = 0; mt < 2; mt++) {
        #pragma unroll
        for (int q = 0; q < 2; q++) {
            const int row = m0 + wm0 + mt * 16 + q * 8 + r;
            #pragma unroll
            for (int nt = 0; nt < 4; nt++) {
                const int n = bn + wn0 + nt * 8 + 2 * kq;
                float v0 = acc[mt][nt][q * 2 + 0];
                float v1 = acc[mt][nt][q * 2 + 1];
                if (n + 1 < N) {
                    float o0 = v0 + bias[n];
                    float o1 = v1 + bias[n + 1];
                    if (relu) { o0 = fmaxf(o0, 0.f); o1 = fmaxf(o1, 0.f); }
                    if (evenN) {
                        float2 p; p.x = o0; p.y = o1;
                        *(float2*)&C[(size_t)row * N + n] = p;
                    } else {
                        C[(size_t)row * N + n] = o0;
                        C[(size_t)row * N + n + 1] = o1;
                    }
                } else if (n < N) {
                    float o0 = v0 + bias[n];
                    if (relu) o0 = fmaxf(o0, 0.f);
                    C[(size_t)row * N + n] = o0;
                }
            }
        }
    }
}

// ---------------- VQ argmin via fp16x3 HMMA: 128 rows/CTA, 8 code-tiles of 128, K=64 ----------------
// score = esq[k] - 2*mu.e_k ; ties -> lowest index. 256 threads, 8 warps (4m x 2n).
// smem u32: Mhi[128][36], Mlo, Ehi, Elo (4608 u32 each) + esq 1024 floats.
__global__ void __launch_bounds__(256, 1) vq_mma()
{
    extern __shared__ uint32_t smv[];
    uint32_t* Mh = smv;             // 4608
    uint32_t* Ml = smv + 4608;
    uint32_t* Eh = smv + 9216;
    uint32_t* El = smv + 13824;
    float* esq_s = (float*)(smv + 18432);

    __shared__ float sbest[8][2][2][8];
    __shared__ int   sidx[8][2][2][8];

    const int tid = threadIdx.x, lane = tid & 31, wid = tid >> 5;
    const int m0 = blockIdx.x * 128;
    const int wm0 = (wid >> 1) * 32, wn0 = (wid & 1) * 64;
    const int r = lane >> 2, kq = lane & 3;

    // mu load: 16 passes of 8 rows; thread: row = ps*8 + wid, col pair j = lane
    #pragma unroll
    for (int ps = 0; ps < 16; ps++) {
        const int row = ps * 8 + wid;
        float2 t = *(const float2*)&g_mu[(size_t)(m0 + row) * LDIM + 2 * lane];
        const float hx = hi32(t.x), hy = hi32(t.y);
        Mh[row * 36 + lane] = packh(hx, hy);
        Ml[row * 36 + lane] = packh(t.x - hx, t.y - hy);
    }
    for (int i = tid; i < KCODE; i += 256) esq_s[i] = g_esq[i];

    float best[2][2];
    int   bidx[2][2];
    #pragma unroll
    for (int i = 0; i < 2; i++)
        #pragma unroll
        for (int j = 0; j < 2; j++) { best[i][j] = 3.4e38f; bidx[i][j] = 0; }

    float2 ev2[16];
    for (int ct = 0; ct < 8; ct++) {
        // prefetch code tile to regs
        #pragma unroll
        for (int ps = 0; ps < 16; ps++) {
            const int row = ps * 8 + wid;
            ev2[ps] = *(const float2*)&g_et[(size_t)(ct * 128 + row) * LDIM + 2 * lane];
        }
        __syncthreads();   // prior compute done reading E (also covers mu/esq on ct=0)
        #pragma unroll
        for (int ps = 0; ps < 16; ps++) {
            const int row = ps * 8 + wid;
            const float hx = hi32(ev2[ps].x), hy = hi32(ev2[ps].y);
            Eh[row * 36 + lane] = packh(hx, hy);
            El[row * 36 + lane] = packh(ev2[ps].x - hx, ev2[ps].y - hy);
        }
        __syncthreads();

        float acc[2][8][4];
        #pragma unroll
        for (int i = 0; i < 2; i++)
            #pragma unroll
            for (int j = 0; j < 8; j++)
                #pragma unroll
                for (int e = 0; e < 4; e++) acc[i][j][e] = 0.f;

        #pragma unroll
        for (int ks = 0; ks < 4; ks++) {
            const int cb = ks * 8 + kq;
            uint32_t ah[2][4], al[2][4], bh[8][2], bl[8][2];
            #pragma unroll
            for (int mt = 0; mt < 2; mt++) {
                const int R0 = (wm0 + mt * 16 + r) * 36;
                const int R1 = R0 + 8 * 36;
                ah[mt][0] = Mh[R0 + cb]; ah[mt][1] = Mh[R1 + cb];
                ah[mt][2] = Mh[R0 + cb + 4]; ah[mt][3] = Mh[R1 + cb + 4];
                al[mt][0] = Ml[R0 + cb]; al[mt][1] = Ml[R1 + cb];
                al[mt][2] = Ml[R0 + cb + 4]; al[mt][3] = Ml[R1 + cb + 4];
            }
            #pragma unroll
            for (int nt = 0; nt < 8; nt++) {
                const int RB = (wn0 + nt * 8 + r) * 36;
                bh[nt][0] = Eh[RB + cb]; bh[nt][1] = Eh[RB + cb + 4];
                bl[nt][0] = El[RB + cb]; bl[nt][1] = El[RB + cb + 4];
            }
            #pragma unroll
            for (int mt = 0; mt < 2; mt++)
                #pragma unroll
                for (int nt = 0; nt < 8; nt++) {
                    mma16(acc[mt][nt], ah[mt], bh[nt]);
                    mma16(acc[mt][nt], ah[mt], bl[nt]);
                    mma16(acc[mt][nt], al[mt], bh[nt]);
                }
        }

        // score + argmin update (ascending code order; strict < keeps first min)
        #pragma unroll
        for (int mt = 0; mt < 2; mt++)
            #pragma unroll
            for (int q = 0; q < 2; q++)
                #pragma unroll
                for (int nt = 0; nt < 8; nt++)
                    #pragma unroll
                    for (int e = 0; e < 2; e++) {
                        const int code = ct * 128 + wn0 + nt * 8 + 2 * kq + e;
                        const float sc = esq_s[code] - 2.f * acc[mt][nt][q * 2 + e];
                        if (sc < best[mt][q]) { best[mt][q] = sc; bidx[mt][q] = code; }
                    }
        __syncthreads();
    }

    // 1) reduce across the 4 lanes of each quad (same rows, different code subsets)
    #pragma unroll
    for (int mt = 0; mt < 2; mt++)
        #pragma unroll
        for (int q = 0; q < 2; q++) {
            float b = best[mt][q]; int ix = bidx[mt][q];
            #pragma unroll
            for (int s = 1; s <= 2; s <<= 1) {
                const float ob = __shfl_xor_sync(0xffffffffu, b, s);
                const int   oi = __shfl_xor_sync(0xffffffffu, ix, s);
                if (ob < b || (ob == b && oi < ix)) { b = ob; ix = oi; }
            }
            if (kq == 0) { sbest[wid][mt][q][r] = b; sidx[wid][mt][q][r] = ix; }
        }
    __syncthreads();

    // 2) merge warp pair (codes split by wn0) and write final index
    if ((wid & 1) == 0 && kq == 0) {
        #pragma unroll
        for (int mt = 0; mt < 2; mt++)
            #pragma unroll
            for (int q = 0; q < 2; q++) {
                float b0 = sbest[wid][mt][q][r];     int i0 = sidx[wid][mt][q][r];
                float b1 = sbest[wid + 1][mt][q][r]; int i1 = sidx[wid + 1][mt][q][r];
                int ix = (b1 < b0 || (b1 == b0 && i1 < i0)) ? i1 : i0;
                g_idx[m0 + wm0 + mt * 16 + r + q * 8] = ix;
            }
    }
}

// ---------------- small prep / VQ-stat kernels ----------------
__global__ void esq_kernel(const float* __restrict__ embed) {
    int k = blockIdx.x * blockDim.x + threadIdx.x;
    if (k < KCODE) {
        float s = 0.f;
        #pragma unroll 8
        for (int l = 0; l < LDIM; l++) { float e = embed[l * KCODE + k]; s += e * e; }
        g_esq[k] = s;
    }
}
__global__ void embed_t_kernel(const float* __restrict__ embed) {
    int i = blockIdx.x * blockDim.x + threadIdx.x;
    if (i < LDIM * KCODE) {
        int l = i >> 10, c = i & (KCODE - 1);
        g_et[c * LDIM + l] = embed[i];
    }
}
__global__ void zero_counts_kernel() {
    int i = blockIdx.x * blockDim.x + threadIdx.x;
    if (i < KCODE) g_counts[i] = 0;
}

__global__ void __launch_bounds__(256) gather_loss_kernel(const float* __restrict__ embed) {
    __shared__ float ps[8];
    const int w = threadIdx.x >> 5, lane = threadIdx.x & 31;
    const int row = blockIdx.x * 8 + w;
    const int idx = g_idx[row];
    float s = 0.f;
    #pragma unroll
    for (int h = 0; h < 2; h++) {
        int l = lane + 32 * h;
        float e = embed[l * KCODE + idx];
        g_q[(size_t)row * LDIM + l] = e;
        float d = e - g_mu[(size_t)row * LDIM + l];
        s += d * d;
    }
    #pragma unroll
    for (int off = 16; off; off >>= 1) s += __shfl_down_sync(0xffffffffu, s, off);
    if (lane == 0) { ps[w] = s; atomicAdd(&g_counts[idx], 1); }
    __syncthreads();
    if (threadIdx.x == 0) {
        float t = 0.f;
        #pragma unroll
        for (int i = 0; i < 8; i++) t += ps[i];
        g_partials[blockIdx.x] = t;
    }
}

__global__ void __launch_bounds__(256) finalize_kernel(float* __restrict__ out) {
    __shared__ float red[256];
    const int t = threadIdx.x;
    float s = 0.f;
    for (int i = t; i < BB / 8; i += 256) s += g_partials[i];
    red[t] = s;
    for (int st = 128; st > 0; st >>= 1) { __syncthreads(); if (t < st) red[t] += red[t + st]; }
    __syncthreads();
    float loss = red[0] / (float)((size_t)BB * LDIM);
    __syncthreads();
    float e = 0.f;
    for (int k = t; k < KCODE; k += 256) {
        float p = (float)g_counts[k] / (float)BB;
        e += p * logf(p + 1e-10f);
    }
    red[t] = e;
    for (int st = 128; st > 0; st >>= 1) { __syncthreads(); if (t < st) red[t] += red[t + st]; }
    __syncthreads();
    if (t == 0) {
        out[(size_t)BB * FDIM] = loss;
        out[(size_t)BB * FDIM + 1] = expf(-red[0]);
    }
}

// ---------------- host launcher ----------------
extern "C" void kernel_launch(void* const* d_in, const int* in_sizes, int n_in,
                              void* d_out, int out_size)
{
    const float* x     = (const float*)d_in[0];
    const float* c     = (const float*)d_in[1];
    const float* fc1_w = (const float*)d_in[2];
    const float* fc1_b = (const float*)d_in[3];
    const float* fc2_w = (const float*)d_in[4];
    const float* fc2_b = (const float*)d_in[5];
    const float* fc3_w = (const float*)d_in[6];
    const float* fc3_b = (const float*)d_in[7];
    const float* mu_w  = (const float*)d_in[8];
    const float* mu_b  = (const float*)d_in[9];
    const float* fc4_w = (const float*)d_in[10];
    const float* fc4_b = (const float*)d_in[11];
    const float* fc5_w = (const float*)d_in[12];
    const float* fc5_b = (const float*)d_in[13];
    const float* fc6_w = (const float*)d_in[14];
    const float* fc6_b = (const float*)d_in[15];
    const float* out_w = (const float*)d_in[16];
    const float* out_b = (const float*)d_in[17];
    const float* embed = (const float*)d_in[18];
    float* out = (float*)d_out;

    float *h1, *h2, *mu, *q;
    cudaGetSymbolAddress((void**)&h1, g_h1);
    cudaGetSymbolAddress((void**)&h2, g_h2);
    cudaGetSymbolAddress((void**)&mu, g_mu);
    cudaGetSymbolAddress((void**)&q,  g_q);

    const int GEMM_SMEM = 2 * 10240 * 4;            // 81920 B
    const int VQ_SMEM   = (18432 + 1024) * 4;       // 77824 B
    cudaFuncSetAttribute(mma_gemm, cudaFuncAttributeMaxDynamicSharedMemorySize, GEMM_SMEM);
    cudaFuncSetAttribute(vq_mma,   cudaFuncAttributeMaxDynamicSharedMemorySize, VQ_SMEM);

    const dim3 blk(512);
    const dim3 g256(2, BB / 128);
    const dim3 g64(1, BB / 128);
    const dim3 g267(3, BB / 128);

    // prep
    esq_kernel<<<4, 256>>>(embed);
    embed_t_kernel<<<(LDIM * KCODE + 255) / 256, 256>>>(embed);
    zero_counts_kernel<<<4, 256>>>();

    // encoder
    mma_gemm<<<g256, blk, GEMM_SMEM>>>(x, FDIM, c, FDIM, fc1_w, fc1_b, h1, HDIM, 2 * FDIM, 1);
    mma_gemm<<<g256, blk, GEMM_SMEM>>>(h1, HDIM, nullptr, 0, fc2_w, fc2_b, h2, HDIM, HDIM, 1);
    mma_gemm<<<g256, blk, GEMM_SMEM>>>(h2, HDIM, nullptr, 0, fc3_w, fc3_b, h1, HDIM, HDIM, 1);
    mma_gemm<<<g64,  blk, GEMM_SMEM>>>(h1, HDIM, nullptr, 0, mu_w, mu_b, mu, LDIM, HDIM, 0);

    // vector quantizer
    vq_mma<<<BB / 128, 256, VQ_SMEM>>>();
    gather_loss_kernel<<<BB / 8, 256>>>(embed);

    // decoder
    mma_gemm<<<g256, blk, GEMM_SMEM>>>(q, LDIM, c, FDIM, fc4_w, fc4_b, h2, HDIM, LDIM + FDIM, 1);
    mma_gemm<<<g256, blk, GEMM_SMEM>>>(h2, HDIM, nullptr, 0, fc5_w, fc5_b, h1, HDIM, HDIM, 1);
    mma_gemm<<<g256, blk, GEMM_SMEM>>>(h1, HDIM, nullptr, 0, fc6_w, fc6_b, h2, HDIM, HDIM, 1);
    mma_gemm<<<g267, blk, GEMM_SMEM>>>(h2, HDIM, nullptr, 0, out_w, out_b, out, FDIM, HDIM, 0);

    // scalars
    finalize_kernel<<<1, 256>>>(out);
}

// round 7
// speedup vs baseline: 3.2631x; 1.0725x over previous
#include <cuda_runtime.h>
#include <cstdint>
#include <math.h>

#define BB 65536
#define FDIM 267
#define HDIM 256
#define LDIM 64
#define KCODE 1024

// ---------------- scratch (device globals) ----------------
__device__ float g_h1[BB * HDIM];
__device__ float g_h2[BB * HDIM];
__device__ float g_mu[BB * LDIM];
__device__ float g_q[BB * LDIM];
__device__ int   g_idx[BB];
__device__ float g_esq[KCODE];
__device__ int   g_counts[KCODE];
__device__ float g_partials[BB / 8];
__device__ float g_et[KCODE * LDIM];   // transposed codebook [code][l]

// ---------------- helpers ----------------
__device__ __forceinline__ float hi32(float a) {
    return __uint_as_float(__float_as_uint(a) & 0xFFFFE000u);
}
__device__ __forceinline__ uint32_t packh(float x, float y) {
    uint32_t d;
    asm("cvt.rn.f16x2.f32 %0, %1, %2;" : "=r"(d) : "f"(y), "f"(x));
    return d;
}
__device__ __forceinline__ uint32_t smem_u32(const void* p) {
    uint32_t a;
    asm("{ .reg .u64 t; cvta.to.shared.u64 t, %1; cvt.u32.u64 %0, t; }" : "=r"(a) : "l"(p));
    return a;
}
__device__ __forceinline__ void ldm_x4(uint32_t* d, uint32_t a) {
    asm volatile("ldmatrix.sync.aligned.m8n8.x4.shared.b16 {%0,%1,%2,%3}, [%4];"
        : "=r"(d[0]), "=r"(d[1]), "=r"(d[2]), "=r"(d[3]) : "r"(a));
}
// d += A(16x16 f16) * B(16x8 f16), fp32 accum
__device__ __forceinline__ void mma16(float* d, const uint32_t* a, const uint32_t* b) {
    asm volatile(
        "mma.sync.aligned.m16n8k16.row.col.f32.f16.f16.f32 "
        "{%0,%1,%2,%3},{%4,%5,%6,%7},{%8,%9},{%0,%1,%2,%3};"
        : "+f"(d[0]), "+f"(d[1]), "+f"(d[2]), "+f"(d[3])
        : "r"(a[0]), "r"(a[1]), "r"(a[2]), "r"(a[3]), "r"(b[0]), "r"(b[1]));
}

// ---------------- fp16x3 HMMA GEMM: C[M,N] = act([A0|A1][M,K] * W[N,K]^T + b) ----------------
// 128x128 CTA tile, BK=32, 16 warps (4m x 4n), warp tile 32x32, ldmatrix fragment loads.
// smem u32 tiles per buf: Ahi[128][20], Alo, Bhi, Blo (2560 u32 each); 2 bufs = 81920 B.
__global__ void __launch_bounds__(512, 1) mma_gemm(
    const float* __restrict__ A0, int W0,
    const float* __restrict__ A1, int W1,
    const float* __restrict__ W, const float* __restrict__ bias,
    float* __restrict__ C, int N, int K, int relu)
{
    extern __shared__ uint32_t smu[];

    const int tid = threadIdx.x, lane = tid & 31, wid = tid >> 5;
    const int m0 = blockIdx.y * 128, bn = blockIdx.x * 128;
    const int wm0 = (wid >> 2) * 32, wn0 = (wid & 3) * 32;
    const int r = lane >> 2, kq = lane & 3;
    const int NC = (K + 31) >> 5;
    const int prow = tid >> 4;     // 0..31 loader row
    const int pj   = tid & 15;     // u32 col (half2 pair index)
    const bool scalA = (A1 != nullptr);
    const bool scalB = (K & 1) != 0;

    // ldmatrix lane addresses (buffer 0)
    const uint32_t sbase = smem_u32(smu);
    const int g = lane >> 3, lr = lane & 7;
    uint32_t aA[2][2], aB[2][2];
    #pragma unroll
    for (int mt = 0; mt < 2; mt++) {
        const uint32_t row = wm0 + mt * 16 + (g & 1) * 8 + lr;
        const uint32_t col = (g >> 1) * 4;
        #pragma unroll
        for (int ks = 0; ks < 2; ks++)
            aA[mt][ks] = sbase + 4u * (row * 20 + col + ks * 8);
    }
    #pragma unroll
    for (int np = 0; np < 2; np++) {
        const uint32_t n = wn0 + (2 * np + (g >> 1)) * 8 + lr;
        const uint32_t col = (g & 1) * 4;
        #pragma unroll
        for (int ks = 0; ks < 2; ks++)
            aB[np][ks] = sbase + 4u * (5120 + n * 20 + col + ks * 8);
    }

    float acc[2][4][4];
    #pragma unroll
    for (int i = 0; i < 2; i++)
        #pragma unroll
        for (int j = 0; j < 4; j++)
            #pragma unroll
            for (int e = 0; e < 4; e++) acc[i][j][e] = 0.f;

    float2 a2[4], b2[4];

    auto prefetch = [&](int c) {
        const int kg = c * 32 + 2 * pj;
        #pragma unroll
        for (int p = 0; p < 4; p++) {
            const int row = p * 32 + prow;
            float ax = 0.f, ay = 0.f, bx = 0.f, by = 0.f;
            if (scalA) {
                if (kg < K)
                    ax = (kg < W0) ? A0[(size_t)(m0 + row) * W0 + kg]
                                   : A1[(size_t)(m0 + row) * W1 + (kg - W0)];
                if (kg + 1 < K)
                    ay = (kg + 1 < W0) ? A0[(size_t)(m0 + row) * W0 + kg + 1]
                                       : A1[(size_t)(m0 + row) * W1 + (kg + 1 - W0)];
            } else if (kg < K) {
                float2 t = *(const float2*)&A0[(size_t)(m0 + row) * W0 + kg];
                ax = t.x; ay = t.y;
            }
            const int n = bn + row;
            if (n < N) {
                if (scalB) {
                    if (kg < K)     bx = W[(size_t)n * K + kg];
                    if (kg + 1 < K) by = W[(size_t)n * K + kg + 1];
                } else if (kg < K) {
                    float2 t = *(const float2*)&W[(size_t)n * K + kg];
                    bx = t.x; by = t.y;
                }
            }
            a2[p] = make_float2(ax, ay);
            b2[p] = make_float2(bx, by);
        }
    };
    auto store = [&](int b) {
        uint32_t* base = smu + b * 10240;
        #pragma unroll
        for (int p = 0; p < 4; p++) {
            const int o = (p * 32 + prow) * 20 + pj;
            float hx = hi32(a2[p].x), hy = hi32(a2[p].y);
            base[o]        = packh(hx, hy);
            base[2560 + o] = packh(a2[p].x - hx, a2[p].y - hy);
            hx = hi32(b2[p].x); hy = hi32(b2[p].y);
            base[5120 + o] = packh(hx, hy);
            base[7680 + o] = packh(b2[p].x - hx, b2[p].y - hy);
        }
    };
    auto compute = [&]() {
        #pragma unroll
        for (int ks = 0; ks < 2; ks++) {
            uint32_t ah[2][4], al[2][4], bh[4][2], bl[4][2];
            ldm_x4(ah[0], aA[0][ks]);
            ldm_x4(ah[1], aA[1][ks]);
            ldm_x4(al[0], aA[0][ks] + 10240u);
            ldm_x4(al[1], aA[1][ks] + 10240u);
            ldm_x4(&bh[0][0], aB[0][ks]);
            ldm_x4(&bh[2][0], aB[1][ks]);
            ldm_x4(&bl[0][0], aB[0][ks] + 10240u);
            ldm_x4(&bl[2][0], aB[1][ks] + 10240u);
            #pragma unroll
            for (int mt = 0; mt < 2; mt++)
                #pragma unroll
                for (int nt = 0; nt < 4; nt++) {
                    mma16(acc[mt][nt], ah[mt], bh[nt]);
                    mma16(acc[mt][nt], ah[mt], bl[nt]);
                    mma16(acc[mt][nt], al[mt], bh[nt]);
                }
        }
    };

    prefetch(0); store(0); __syncthreads();
    int32_t dshift = 40960;
    for (int c = 0; c < NC; c++) {
        if (c + 1 < NC) prefetch(c + 1);
        compute();
        if (c + 1 < NC) store((c + 1) & 1);
        __syncthreads();
        if (c + 1 < NC) {
            #pragma unroll
            for (int mt = 0; mt < 2; mt++)
                #pragma unroll
                for (int ks = 0; ks < 2; ks++) { aA[mt][ks] += dshift; aB[mt][ks] += dshift; }
            dshift = -dshift;
        }
    }

    // epilogue: bias + relu, float2 stores when aligned
    const bool evenN = (N & 1) == 0;
    #pragma unroll
    for (int mt = 0; mt < 2; mt++) {
        #pragma unroll
        for (int q = 0; q < 2; q++) {
            const int row = m0 + wm0 + mt * 16 + q * 8 + r;
            #pragma unroll
            for (int nt = 0; nt < 4; nt++) {
                const int n = bn + wn0 + nt * 8 + 2 * kq;
                float v0 = acc[mt][nt][q * 2 + 0];
                float v1 = acc[mt][nt][q * 2 + 1];
                if (n + 1 < N) {
                    float o0 = v0 + bias[n];
                    float o1 = v1 + bias[n + 1];
                    if (relu) { o0 = fmaxf(o0, 0.f); o1 = fmaxf(o1, 0.f); }
                    if (evenN) {
                        float2 p; p.x = o0; p.y = o1;
                        *(float2*)&C[(size_t)row * N + n] = p;
                    } else {
                        C[(size_t)row * N + n] = o0;
                        C[(size_t)row * N + n + 1] = o1;
                    }
                } else if (n < N) {
                    float o0 = v0 + bias[n];
                    if (relu) o0 = fmaxf(o0, 0.f);
                    C[(size_t)row * N + n] = o0;
                }
            }
        }
    }
}

// ---------------- VQ argmin via fp16x3 HMMA + ldmatrix ----------------
// 128 rows/CTA, 8 code-tiles of 128, K=64; score = esq[k] - 2*mu.e_k ; ties -> lowest index.
// smem u32: Mhi[128][36], Mlo, Ehi, Elo (4608 u32 each) + esq 1024 floats.
__global__ void __launch_bounds__(256, 1) vq_mma()
{
    extern __shared__ uint32_t smv[];
    uint32_t* Mh = smv;             // 4608
    uint32_t* Ml = smv + 4608;
    uint32_t* Eh = smv + 9216;
    uint32_t* El = smv + 13824;
    float* esq_s = (float*)(smv + 18432);

    __shared__ float sbest[8][2][2][8];
    __shared__ int   sidx[8][2][2][8];

    const int tid = threadIdx.x, lane = tid & 31, wid = tid >> 5;
    const int m0 = blockIdx.x * 128;
    const int wm0 = (wid >> 1) * 32, wn0 = (wid & 1) * 64;
    const int r = lane >> 2, kq = lane & 3;

    // ldmatrix lane addresses
    const uint32_t sbase = smem_u32(smv);
    const int g = lane >> 3, lr = lane & 7;
    uint32_t aM[2], aE[4];
    #pragma unroll
    for (int mt = 0; mt < 2; mt++) {
        const uint32_t row = wm0 + mt * 16 + (g & 1) * 8 + lr;
        aM[mt] = sbase + 4u * (row * 36 + (g >> 1) * 4);
    }
    #pragma unroll
    for (int np = 0; np < 4; np++) {
        const uint32_t n = wn0 + (2 * np + (g >> 1)) * 8 + lr;
        aE[np] = sbase + 4u * (9216 + n * 36 + (g & 1) * 4);
    }

    // mu load: 16 passes of 8 rows
    #pragma unroll
    for (int ps = 0; ps < 16; ps++) {
        const int row = ps * 8 + wid;
        float2 t = *(const float2*)&g_mu[(size_t)(m0 + row) * LDIM + 2 * lane];
        const float hx = hi32(t.x), hy = hi32(t.y);
        Mh[row * 36 + lane] = packh(hx, hy);
        Ml[row * 36 + lane] = packh(t.x - hx, t.y - hy);
    }
    for (int i = tid; i < KCODE; i += 256) esq_s[i] = g_esq[i];

    float best[2][2];
    int   bidx[2][2];
    #pragma unroll
    for (int i = 0; i < 2; i++)
        #pragma unroll
        for (int j = 0; j < 2; j++) { best[i][j] = 3.4e38f; bidx[i][j] = 0; }

    float2 ev2[16];
    for (int ct = 0; ct < 8; ct++) {
        // prefetch code tile to regs
        #pragma unroll
        for (int ps = 0; ps < 16; ps++) {
            const int row = ps * 8 + wid;
            ev2[ps] = *(const float2*)&g_et[(size_t)(ct * 128 + row) * LDIM + 2 * lane];
        }
        __syncthreads();   // prior compute done reading E (also covers mu/esq on ct=0)
        #pragma unroll
        for (int ps = 0; ps < 16; ps++) {
            const int row = ps * 8 + wid;
            const float hx = hi32(ev2[ps].x), hy = hi32(ev2[ps].y);
            Eh[row * 36 + lane] = packh(hx, hy);
            El[row * 36 + lane] = packh(ev2[ps].x - hx, ev2[ps].y - hy);
        }
        __syncthreads();

        float acc[2][8][4];
        #pragma unroll
        for (int i = 0; i < 2; i++)
            #pragma unroll
            for (int j = 0; j < 8; j++)
                #pragma unroll
                for (int e = 0; e < 4; e++) acc[i][j][e] = 0.f;

        #pragma unroll
        for (int ks = 0; ks < 4; ks++) {
            const uint32_t ko = ks * 32u;
            uint32_t ah[2][4], al[2][4], bh[8][2], bl[8][2];
            ldm_x4(ah[0], aM[0] + ko);
            ldm_x4(ah[1], aM[1] + ko);
            ldm_x4(al[0], aM[0] + ko + 18432u);
            ldm_x4(al[1], aM[1] + ko + 18432u);
            #pragma unroll
            for (int np = 0; np < 4; np++) {
                ldm_x4(&bh[2 * np][0], aE[np] + ko);
                ldm_x4(&bl[2 * np][0], aE[np] + ko + 18432u);
            }
            #pragma unroll
            for (int mt = 0; mt < 2; mt++)
                #pragma unroll
                for (int nt = 0; nt < 8; nt++) {
                    mma16(acc[mt][nt], ah[mt], bh[nt]);
                    mma16(acc[mt][nt], ah[mt], bl[nt]);
                    mma16(acc[mt][nt], al[mt], bh[nt]);
                }
        }

        // score + argmin update (ascending code order; strict < keeps first min)
        #pragma unroll
        for (int mt = 0; mt < 2; mt++)
            #pragma unroll
            for (int q = 0; q < 2; q++)
                #pragma unroll
                for (int nt = 0; nt < 8; nt++)
                    #pragma unroll
                    for (int e = 0; e < 2; e++) {
                        const int code = ct * 128 + wn0 + nt * 8 + 2 * kq + e;
                        const float sc = esq_s[code] - 2.f * acc[mt][nt][q * 2 + e];
                        if (sc < best[mt][q]) { best[mt][q] = sc; bidx[mt][q] = code; }
                    }
        __syncthreads();
    }

    // 1) reduce across the 4 lanes of each quad (same rows, different code subsets)
    #pragma unroll
    for (int mt = 0; mt < 2; mt++)
        #pragma unroll
        for (int q = 0; q < 2; q++) {
            float b = best[mt][q]; int ix = bidx[mt][q];
            #pragma unroll
            for (int s = 1; s <= 2; s <<= 1) {
                const float ob = __shfl_xor_sync(0xffffffffu, b, s);
                const int   oi = __shfl_xor_sync(0xffffffffu, ix, s);
                if (ob < b || (ob == b && oi < ix)) { b = ob; ix = oi; }
            }
            if (kq == 0) { sbest[wid][mt][q][r] = b; sidx[wid][mt][q][r] = ix; }
        }
    __syncthreads();

    // 2) merge warp pair (codes split by wn0) and write final index
    if ((wid & 1) == 0 && kq == 0) {
        #pragma unroll
        for (int mt = 0; mt < 2; mt++)
            #pragma unroll
            for (int q = 0; q < 2; q++) {
                float b0 = sbest[wid][mt][q][r];     int i0 = sidx[wid][mt][q][r];
                float b1 = sbest[wid + 1][mt][q][r]; int i1 = sidx[wid + 1][mt][q][r];
                int ix = (b1 < b0 || (b1 == b0 && i1 < i0)) ? i1 : i0;
                g_idx[m0 + wm0 + mt * 16 + r + q * 8] = ix;
            }
    }
}

// ---------------- small prep / VQ-stat kernels ----------------
__global__ void esq_kernel(const float* __restrict__ embed) {
    int k = blockIdx.x * blockDim.x + threadIdx.x;
    if (k < KCODE) {
        float s = 0.f;
        #pragma unroll 8
        for (int l = 0; l < LDIM; l++) { float e = embed[l * KCODE + k]; s += e * e; }
        g_esq[k] = s;
    }
}
__global__ void embed_t_kernel(const float* __restrict__ embed) {
    int i = blockIdx.x * blockDim.x + threadIdx.x;
    if (i < LDIM * KCODE) {
        int l = i >> 10, c = i & (KCODE - 1);
        g_et[c * LDIM + l] = embed[i];
    }
}
__global__ void zero_counts_kernel() {
    int i = blockIdx.x * blockDim.x + threadIdx.x;
    if (i < KCODE) g_counts[i] = 0;
}

__global__ void __launch_bounds__(256) gather_loss_kernel(const float* __restrict__ embed) {
    __shared__ float ps[8];
    const int w = threadIdx.x >> 5, lane = threadIdx.x & 31;
    const int row = blockIdx.x * 8 + w;
    const int idx = g_idx[row];
    float s = 0.f;
    #pragma unroll
    for (int h = 0; h < 2; h++) {
        int l = lane + 32 * h;
        float e = embed[l * KCODE + idx];
        g_q[(size_t)row * LDIM + l] = e;
        float d = e - g_mu[(size_t)row * LDIM + l];
        s += d * d;
    }
    #pragma unroll
    for (int off = 16; off; off >>= 1) s += __shfl_down_sync(0xffffffffu, s, off);
    if (lane == 0) { ps[w] = s; atomicAdd(&g_counts[idx], 1); }
    __syncthreads();
    if (threadIdx.x == 0) {
        float t = 0.f;
        #pragma unroll
        for (int i = 0; i < 8; i++) t += ps[i];
        g_partials[blockIdx.x] = t;
    }
}

__global__ void __launch_bounds__(256) finalize_kernel(float* __restrict__ out) {
    __shared__ float red[256];
    const int t = threadIdx.x;
    float s = 0.f;
    for (int i = t; i < BB / 8; i += 256) s += g_partials[i];
    red[t] = s;
    for (int st = 128; st > 0; st >>= 1) { __syncthreads(); if (t < st) red[t] += red[t + st]; }
    __syncthreads();
    float loss = red[0] / (float)((size_t)BB * LDIM);
    __syncthreads();
    float e = 0.f;
    for (int k = t; k < KCODE; k += 256) {
        float p = (float)g_counts[k] / (float)BB;
        e += p * logf(p + 1e-10f);
    }
    red[t] = e;
    for (int st = 128; st > 0; st >>= 1) { __syncthreads(); if (t < st) red[t] += red[t + st]; }
    __syncthreads();
    if (t == 0) {
        out[(size_t)BB * FDIM] = loss;
        out[(size_t)BB * FDIM + 1] = expf(-red[0]);
    }
}

// ---------------- host launcher ----------------
extern "C" void kernel_launch(void* const* d_in, const int* in_sizes, int n_in,
                              void* d_out, int out_size)
{
    const float* x     = (const float*)d_in[0];
    const float* c     = (const float*)d_in[1];
    const float* fc1_w = (const float*)d_in[2];
    const float* fc1_b = (const float*)d_in[3];
    const float* fc2_w = (const float*)d_in[4];
    const float* fc2_b = (const float*)d_in[5];
    const float* fc3_w = (const float*)d_in[6];
    const float* fc3_b = (const float*)d_in[7];
    const float* mu_w  = (const float*)d_in[8];
    const float* mu_b  = (const float*)d_in[9];
    const float* fc4_w = (const float*)d_in[10];
    const float* fc4_b = (const float*)d_in[11];
    const float* fc5_w = (const float*)d_in[12];
    const float* fc5_b = (const float*)d_in[13];
    const float* fc6_w = (const float*)d_in[14];
    const float* fc6_b = (const float*)d_in[15];
    const float* out_w = (const float*)d_in[16];
    const float* out_b = (const float*)d_in[17];
    const float* embed = (const float*)d_in[18];
    float* out = (float*)d_out;

    float *h1, *h2, *mu, *q;
    cudaGetSymbolAddress((void**)&h1, g_h1);
    cudaGetSymbolAddress((void**)&h2, g_h2);
    cudaGetSymbolAddress((void**)&mu, g_mu);
    cudaGetSymbolAddress((void**)&q,  g_q);

    const int GEMM_SMEM = 2 * 10240 * 4;            // 81920 B
    const int VQ_SMEM   = (18432 + 1024) * 4;       // 77824 B
    cudaFuncSetAttribute(mma_gemm, cudaFuncAttributeMaxDynamicSharedMemorySize, GEMM_SMEM);
    cudaFuncSetAttribute(vq_mma,   cudaFuncAttributeMaxDynamicSharedMemorySize, VQ_SMEM);

    const dim3 blk(512);
    const dim3 g256(2, BB / 128);
    const dim3 g64(1, BB / 128);
    const dim3 g267(3, BB / 128);

    // prep
    esq_kernel<<<4, 256>>>(embed);
    embed_t_kernel<<<(LDIM * KCODE + 255) / 256, 256>>>(embed);
    zero_counts_kernel<<<4, 256>>>();

    // encoder
    mma_gemm<<<g256, blk, GEMM_SMEM>>>(x, FDIM, c, FDIM, fc1_w, fc1_b, h1, HDIM, 2 * FDIM, 1);
    mma_gemm<<<g256, blk, GEMM_SMEM>>>(h1, HDIM, nullptr, 0, fc2_w, fc2_b, h2, HDIM, HDIM, 1);
    mma_gemm<<<g256, blk, GEMM_SMEM>>>(h2, HDIM, nullptr, 0, fc3_w, fc3_b, h1, HDIM, HDIM, 1);
    mma_gemm<<<g64,  blk, GEMM_SMEM>>>(h1, HDIM, nullptr, 0, mu_w, mu_b, mu, LDIM, HDIM, 0);

    // vector quantizer
    vq_mma<<<BB / 128, 256, VQ_SMEM>>>();
    gather_loss_kernel<<<BB / 8, 256>>>(embed);

    // decoder
    mma_gemm<<<g256, blk, GEMM_SMEM>>>(q, LDIM, c, FDIM, fc4_w, fc4_b, h2, HDIM, LDIM + FDIM, 1);
    mma_gemm<<<g256, blk, GEMM_SMEM>>>(h2, HDIM, nullptr, 0, fc5_w, fc5_b, h1, HDIM, HDIM, 1);
    mma_gemm<<<g256, blk, GEMM_SMEM>>>(h1, HDIM, nullptr, 0, fc6_w, fc6_b, h2, HDIM, HDIM, 1);
    mma_gemm<<<g267, blk, GEMM_SMEM>>>(h2, HDIM, nullptr, 0, out_w, out_b, out, FDIM, HDIM, 0);

    // scalars
    finalize_kernel<<<1, 256>>>(out);
}